// round 2
// baseline (speedup 1.0000x reference)
#include <cuda_runtime.h>
#include <math.h>

#define N_NODES 20000
#define N_EDGES 320000
#define D 128
#define KEMB 288
#define PRED 24
#define EPSV 1e-5f

#define TM 64
#define XS_STRIDE 130
#define SMEM_BYTES ((TM * XS_STRIDE + D * D) * 4)

// ---------------- scratch (device globals; no runtime alloc allowed) ----------
__device__ float g_h[N_NODES * D];
__device__ float g_e[N_EDGES * D];
__device__ float g_agg[N_NODES * D];
__device__ float g_inv_cnt[N_NODES];
__device__ int   g_deg[N_NODES];
__device__ int   g_ptr[N_NODES + 1];
__device__ int   g_off[N_NODES];
__device__ int   g_idx[N_EDGES];

// ---------------- helpers ------------------------------------------------------
__device__ __forceinline__ float gelu_f(float x) {
    // JAX approximate gelu: 0.5*x*(1+tanh(sqrt(2/pi)*(x+0.044715*x^3)))
    float u = 0.7978845608028654f * (x + 0.044715f * x * x * x);
    u = fminf(40.f, fmaxf(-40.f, u));
    float t = __expf(2.f * u);
    float th = __fdividef(t - 1.f, t + 1.f);
    return 0.5f * x * (1.f + th);
}

__device__ __forceinline__ void zero_acc(float acc[8][8]) {
#pragma unroll
    for (int i = 0; i < 8; i++)
#pragma unroll
        for (int j = 0; j < 8; j++) acc[i][j] = 0.f;
}

// stage W tile [rows x 128] from global into smem (rows*32 float4's)
__device__ __forceinline__ void stage_W(float* Ws, const float* __restrict__ src,
                                        int n4, int tid) {
    for (int idx = tid; idx < n4; idx += 128)
        ((float4*)Ws)[idx] = __ldg(((const float4*)src) + idx);
}

// stage 64 rows x 128 cols directly (row-aligned source)
__device__ __forceinline__ void stage_X_rows(float* Xs, const float* __restrict__ src,
                                             int row0, int M, int tid) {
    for (int idx = tid; idx < TM * 64; idx += 128) {
        int r = idx >> 6, c = idx & 63;
        int row = row0 + r;
        float2 v = make_float2(0.f, 0.f);
        if (row < M) v = __ldg(((const float2*)(src + (size_t)row * D)) + c);
        *(float2*)(Xs + r * XS_STRIDE + 2 * c) = v;
    }
}

// stage 64 rows x 128 cols gathered via index array
__device__ __forceinline__ void stage_X_gather(float* Xs, const float* __restrict__ src,
                                               const int* __restrict__ gidx,
                                               int row0, int M, int tid) {
    for (int idx = tid; idx < TM * 64; idx += 128) {
        int r = idx >> 6, c = idx & 63;
        int row = row0 + r;
        float2 v = make_float2(0.f, 0.f);
        if (row < M) {
            int g = __ldg(gidx + row);
            v = __ldg(((const float2*)(src + (size_t)g * D)) + c);
        }
        *(float2*)(Xs + r * XS_STRIDE + 2 * c) = v;
    }
}

// acc += Xs[64xK] * Ws[Kx128]  (8x8 micro-tile per thread; 128 threads = 8x16)
__device__ __forceinline__ void gemm128(const float* Xs, const float* Ws,
                                        float acc[8][8], int K, int ty, int tx) {
    const float* xb = Xs + ty * 8 * XS_STRIDE;
    const float* wb = Ws + tx * 8;
#pragma unroll 4
    for (int k = 0; k < K; k++) {
        float4 b0 = *(const float4*)(wb + k * D);
        float4 b1 = *(const float4*)(wb + k * D + 4);
        float bv[8] = {b0.x, b0.y, b0.z, b0.w, b1.x, b1.y, b1.z, b1.w};
#pragma unroll
        for (int i = 0; i < 8; i++) {
            float a = xb[i * XS_STRIDE + k];
#pragma unroll
            for (int j = 0; j < 8; j++) acc[i][j] += a * bv[j];
        }
    }
}

__device__ __forceinline__ void acc_to_X(float* Xs, const float acc[8][8], int ty, int tx) {
#pragma unroll
    for (int i = 0; i < 8; i++)
#pragma unroll
        for (int jp = 0; jp < 4; jp++)
            *(float2*)(Xs + (ty * 8 + i) * XS_STRIDE + tx * 8 + 2 * jp) =
                make_float2(acc[i][2 * jp], acc[i][2 * jp + 1]);
}

// bias + gelu + LayerNorm on acc (per-row reduction via shfl over the 16 tx lanes)
__device__ __forceinline__ void mlp_epilogue(float acc[8][8],
                                             const float* __restrict__ bias,
                                             const float* __restrict__ lg,
                                             const float* __restrict__ lb, int tx) {
    float bv[8], gv[8], bev[8];
#pragma unroll
    for (int j = 0; j < 8; j++) {
        bv[j] = __ldg(bias + tx * 8 + j);
        gv[j] = __ldg(lg + tx * 8 + j);
        bev[j] = __ldg(lb + tx * 8 + j);
    }
#pragma unroll
    for (int i = 0; i < 8; i++) {
        float s1 = 0.f, s2 = 0.f;
#pragma unroll
        for (int j = 0; j < 8; j++) {
            float z = gelu_f(acc[i][j] + bv[j]);
            acc[i][j] = z;
            s1 += z;
            s2 += z * z;
        }
#pragma unroll
        for (int o = 8; o >= 1; o >>= 1) {
            s1 += __shfl_xor_sync(0xffffffffu, s1, o);
            s2 += __shfl_xor_sync(0xffffffffu, s2, o);
        }
        float m = s1 * (1.f / D);
        float var = s2 * (1.f / D) - m * m;
        float rs = rsqrtf(var + EPSV);
#pragma unroll
        for (int j = 0; j < 8; j++)
            acc[i][j] = (acc[i][j] - m) * rs * gv[j] + bev[j];
    }
}

__device__ __forceinline__ void residual_store(float* dst, const float acc[8][8],
                                               int row0, int M, int ty, int tx) {
#pragma unroll
    for (int i = 0; i < 8; i++) {
        int row = row0 + ty * 8 + i;
        if (row < M) {
            float2* p = (float2*)(dst + (size_t)row * D + tx * 8);
#pragma unroll
            for (int jp = 0; jp < 4; jp++) {
                float2 v = p[jp];
                v.x += acc[i][2 * jp];
                v.y += acc[i][2 * jp + 1];
                p[jp] = v;
            }
        }
    }
}

__device__ __forceinline__ void plain_store(float* dst, const float acc[8][8],
                                            int row0, int M, int ty, int tx) {
#pragma unroll
    for (int i = 0; i < 8; i++) {
        int row = row0 + ty * 8 + i;
        if (row < M) {
            float2* p = (float2*)(dst + (size_t)row * D + tx * 8);
#pragma unroll
            for (int jp = 0; jp < 4; jp++)
                p[jp] = make_float2(acc[i][2 * jp], acc[i][2 * jp + 1]);
        }
    }
}

// ---------------- CSR construction --------------------------------------------
__global__ void k_zero_deg() {
    int i = blockIdx.x * blockDim.x + threadIdx.x;
    if (i < N_NODES) g_deg[i] = 0;
}

__global__ void k_hist(const int* __restrict__ recv) {
    int i = blockIdx.x * blockDim.x + threadIdx.x;
    if (i < N_EDGES) atomicAdd(&g_deg[recv[i]], 1);
}

__global__ void k_scan() {  // single block, 1024 threads
    __shared__ int partial[1024];
    const int CH = (N_NODES + 1023) / 1024;
    int t = threadIdx.x;
    int start = t * CH;
    int end = min(start + CH, N_NODES);
    int s = 0;
    for (int i = start; i < end; i++) s += g_deg[i];
    partial[t] = s;
    __syncthreads();
    for (int o = 1; o < 1024; o <<= 1) {
        int v = (t >= o) ? partial[t - o] : 0;
        __syncthreads();
        partial[t] += v;
        __syncthreads();
    }
    int run = partial[t] - s;  // exclusive prefix
    for (int i = start; i < end; i++) {
        int d = g_deg[i];
        g_ptr[i] = run;
        g_off[i] = run;
        g_inv_cnt[i] = 1.0f / (float)max(d, 1);
        run += d;
    }
    if (t == 0) g_ptr[N_NODES] = N_EDGES;
}

__global__ void k_scatter(const int* __restrict__ recv) {
    int i = blockIdx.x * blockDim.x + threadIdx.x;
    if (i < N_EDGES) {
        int p = atomicAdd(&g_off[recv[i]], 1);
        g_idx[p] = i;
    }
}

__global__ void k_sortlists() {  // deterministic order within each node's list
    int n = blockIdx.x * blockDim.x + threadIdx.x;
    if (n >= N_NODES) return;
    int b = g_ptr[n], e2 = g_ptr[n + 1];
    for (int i = b + 1; i < e2; i++) {
        int v = g_idx[i];
        int j = i - 1;
        while (j >= b && g_idx[j] > v) {
            g_idx[j + 1] = g_idx[j];
            j--;
        }
        g_idx[j + 1] = v;
    }
}

// ---------------- embeddings ---------------------------------------------------
__global__ void __launch_bounds__(128, 2) k_node_emb(const float* __restrict__ nodes,
                                                     const float* __restrict__ w,
                                                     const float* __restrict__ b) {
    extern __shared__ float sm[];
    float* Xs = sm;
    float* Ws = sm + TM * XS_STRIDE;
    int tid = threadIdx.x, ty = tid >> 4, tx = tid & 15;
    int row0 = blockIdx.x * TM;
    float acc[8][8];
    zero_acc(acc);
    for (int s = 0; s < 3; s++) {  // K = 288 in 3 chunks of 96
        __syncthreads();
        for (int idx = tid; idx < TM * 48; idx += 128) {
            int r = idx / 48, c = idx % 48;
            int row = row0 + r;
            float2 v = make_float2(0.f, 0.f);
            if (row < N_NODES)
                v = __ldg(((const float2*)(nodes + (size_t)row * KEMB + s * 96)) + c);
            *(float2*)(Xs + r * XS_STRIDE + 2 * c) = v;
        }
        stage_W(Ws, w + s * 96 * D, 96 * 32, tid);
        __syncthreads();
        gemm128(Xs, Ws, acc, 96, ty, tx);
    }
    float bv[8];
#pragma unroll
    for (int j = 0; j < 8; j++) bv[j] = __ldg(b + tx * 8 + j);
#pragma unroll
    for (int i = 0; i < 8; i++)
#pragma unroll
        for (int j = 0; j < 8; j++) acc[i][j] += bv[j];
    plain_store(g_h, acc, row0, N_NODES, ty, tx);
}

__global__ void k_edge_emb(const float* __restrict__ edges,
                           const float* __restrict__ w, const float* __restrict__ b) {
    int idx = blockIdx.x * blockDim.x + threadIdx.x;
    if (idx >= N_EDGES * 32) return;
    int ei = idx >> 5, c4 = idx & 31;
    float e0 = __ldg(edges + ei * 2);
    float e1 = __ldg(edges + ei * 2 + 1);
    float4 w0 = __ldg(((const float4*)w) + c4);
    float4 w1 = __ldg(((const float4*)(w + D)) + c4);
    float4 bb = __ldg(((const float4*)b) + c4);
    float4 r;
    r.x = e0 * w0.x + e1 * w1.x + bb.x;
    r.y = e0 * w0.y + e1 * w1.y + bb.y;
    r.z = e0 * w0.z + e1 * w1.z + bb.z;
    r.w = e0 * w0.w + e1 * w1.w + bb.w;
    ((float4*)(g_e + (size_t)ei * D))[c4] = r;
}

// ---------------- fused edge update -------------------------------------------
__global__ void __launch_bounds__(128, 2) k_edge_fused(
    const int* __restrict__ senders, const int* __restrict__ receivers,
    const float* __restrict__ pw, const float* __restrict__ pb,
    const float* __restrict__ mw, const float* __restrict__ mb,
    const float* __restrict__ lg, const float* __restrict__ lb) {
    extern __shared__ float sm[];
    float* Xs = sm;
    float* Ws = sm + TM * XS_STRIDE;
    int tid = threadIdx.x, ty = tid >> 4, tx = tid & 15;
    int row0 = blockIdx.x * TM;
    float acc[8][8];
    zero_acc(acc);
    // proj: K=384 in 3 chunks (e, h[senders], h[receivers])
    for (int s = 0; s < 3; s++) {
        __syncthreads();
        if (s == 0)
            stage_X_rows(Xs, g_e, row0, N_EDGES, tid);
        else
            stage_X_gather(Xs, g_h, (s == 1) ? senders : receivers, row0, N_EDGES, tid);
        stage_W(Ws, pw + s * 128 * D, 128 * 32, tid);
        __syncthreads();
        gemm128(Xs, Ws, acc, 128, ty, tx);
    }
    {
        float bv[8];
#pragma unroll
        for (int j = 0; j < 8; j++) bv[j] = __ldg(pb + tx * 8 + j);
#pragma unroll
        for (int i = 0; i < 8; i++)
#pragma unroll
            for (int j = 0; j < 8; j++) acc[i][j] += bv[j];
    }
    // MLP x2: LN(gelu(x@W + b))
    for (int m = 0; m < 2; m++) {
        __syncthreads();
        acc_to_X(Xs, acc, ty, tx);
        stage_W(Ws, mw + m * D * D, 128 * 32, tid);
        __syncthreads();
        zero_acc(acc);
        gemm128(Xs, Ws, acc, 128, ty, tx);
        mlp_epilogue(acc, mb + m * D, lg + m * D, lb + m * D, tx);
    }
    residual_store(g_e, acc, row0, N_EDGES, ty, tx);
}

// ---------------- scatter-mean aggregation (pull via CSR) ----------------------
__global__ void __launch_bounds__(256) k_agg() {
    int warp = (blockIdx.x * 256 + threadIdx.x) >> 5;
    int lane = threadIdx.x & 31;
    if (warp >= N_NODES) return;
    int b = g_ptr[warp], e2 = g_ptr[warp + 1];
    float4 a = make_float4(0.f, 0.f, 0.f, 0.f);
    for (int p = b; p < e2; p++) {
        int ei = g_idx[p];
        float4 v = *(const float4*)(g_e + (size_t)ei * D + lane * 4);
        a.x += v.x; a.y += v.y; a.z += v.z; a.w += v.w;
    }
    float ic = g_inv_cnt[warp];
    *(float4*)(g_agg + (size_t)warp * D + lane * 4) =
        make_float4(a.x * ic, a.y * ic, a.z * ic, a.w * ic);
}

// ---------------- fused node update -------------------------------------------
__global__ void __launch_bounds__(128, 2) k_node_fused(
    const float* __restrict__ pw, const float* __restrict__ pb,
    const float* __restrict__ mw, const float* __restrict__ mb,
    const float* __restrict__ lg, const float* __restrict__ lb) {
    extern __shared__ float sm[];
    float* Xs = sm;
    float* Ws = sm + TM * XS_STRIDE;
    int tid = threadIdx.x, ty = tid >> 4, tx = tid & 15;
    int row0 = blockIdx.x * TM;
    float acc[8][8];
    zero_acc(acc);
    for (int s = 0; s < 2; s++) {  // K=256: [h, agg]
        __syncthreads();
        stage_X_rows(Xs, (s == 0) ? g_h : g_agg, row0, N_NODES, tid);
        stage_W(Ws, pw + s * 128 * D, 128 * 32, tid);
        __syncthreads();
        gemm128(Xs, Ws, acc, 128, ty, tx);
    }
    {
        float bv[8];
#pragma unroll
        for (int j = 0; j < 8; j++) bv[j] = __ldg(pb + tx * 8 + j);
#pragma unroll
        for (int i = 0; i < 8; i++)
#pragma unroll
            for (int j = 0; j < 8; j++) acc[i][j] += bv[j];
    }
    for (int m = 0; m < 2; m++) {
        __syncthreads();
        acc_to_X(Xs, acc, ty, tx);
        stage_W(Ws, mw + m * D * D, 128 * 32, tid);
        __syncthreads();
        zero_acc(acc);
        gemm128(Xs, Ws, acc, 128, ty, tx);
        mlp_epilogue(acc, mb + m * D, lg + m * D, lb + m * D, tx);
    }
    residual_store(g_h, acc, row0, N_NODES, ty, tx);
}

// ---------------- output head --------------------------------------------------
__global__ void __launch_bounds__(128, 2) k_out(
    const float* __restrict__ w1, const float* __restrict__ b1,
    const float* __restrict__ lg, const float* __restrict__ lb,
    const float* __restrict__ pw, const float* __restrict__ pb,
    float* __restrict__ out) {
    extern __shared__ float sm[];
    float* Xs = sm;
    float* Ws = sm + TM * XS_STRIDE;
    int tid = threadIdx.x, ty = tid >> 4, tx = tid & 15;
    int row0 = blockIdx.x * TM;
    float acc[8][8];
    zero_acc(acc);
    stage_X_rows(Xs, g_h, row0, N_NODES, tid);
    stage_W(Ws, w1, 128 * 32, tid);
    __syncthreads();
    gemm128(Xs, Ws, acc, 128, ty, tx);
    mlp_epilogue(acc, b1, lg, lb, tx);
    __syncthreads();
    acc_to_X(Xs, acc, ty, tx);
    stage_W(Ws, pw, (D * PRED) / 4, tid);  // 128x24 proj weights
    __syncthreads();
    for (int idx = tid; idx < TM * PRED; idx += 128) {
        int r = idx / PRED, p = idx % PRED;
        int row = row0 + r;
        if (row < N_NODES) {
            float s = __ldg(pb + p);
            const float* xr = Xs + r * XS_STRIDE;
#pragma unroll 4
            for (int k = 0; k < D; k++) s += xr[k] * Ws[k * PRED + p];
            out[(size_t)row * PRED + p] = s;
        }
    }
}

// ---------------- launch -------------------------------------------------------
extern "C" void kernel_launch(void* const* d_in, const int* in_sizes, int n_in,
                              void* d_out, int out_size) {
    const float* nodes = (const float*)d_in[0];
    const float* edges = (const float*)d_in[1];
    const int* senders = (const int*)d_in[2];
    const int* receivers = (const int*)d_in[3];
    const float* w_ne = (const float*)d_in[4];
    const float* b_ne = (const float*)d_in[5];
    const float* w_ee = (const float*)d_in[6];
    const float* b_ee = (const float*)d_in[7];
    const float* epw = (const float*)d_in[8];
    const float* epb = (const float*)d_in[9];
    const float* npw = (const float*)d_in[10];
    const float* npb = (const float*)d_in[11];
    const float* emw = (const float*)d_in[12];
    const float* emb_ = (const float*)d_in[13];
    const float* elg = (const float*)d_in[14];
    const float* elb = (const float*)d_in[15];
    const float* nmw = (const float*)d_in[16];
    const float* nmb = (const float*)d_in[17];
    const float* nlg = (const float*)d_in[18];
    const float* nlb = (const float*)d_in[19];
    const float* ow = (const float*)d_in[20];
    const float* ob = (const float*)d_in[21];
    const float* og = (const float*)d_in[22];
    const float* obeta = (const float*)d_in[23];
    const float* pw = (const float*)d_in[24];
    const float* pb = (const float*)d_in[25];
    float* out = (float*)d_out;

    cudaFuncSetAttribute(k_edge_fused, cudaFuncAttributeMaxDynamicSharedMemorySize, SMEM_BYTES);
    cudaFuncSetAttribute(k_node_fused, cudaFuncAttributeMaxDynamicSharedMemorySize, SMEM_BYTES);
    cudaFuncSetAttribute(k_node_emb, cudaFuncAttributeMaxDynamicSharedMemorySize, SMEM_BYTES);
    cudaFuncSetAttribute(k_out, cudaFuncAttributeMaxDynamicSharedMemorySize, SMEM_BYTES);

    // CSR build (deterministic: per-node lists sorted by edge id)
    k_zero_deg<<<(N_NODES + 255) / 256, 256>>>();
    k_hist<<<(N_EDGES + 255) / 256, 256>>>(receivers);
    k_scan<<<1, 1024>>>();
    k_scatter<<<(N_EDGES + 255) / 256, 256>>>(receivers);
    k_sortlists<<<(N_NODES + 255) / 256, 256>>>();

    // embeddings
    k_node_emb<<<(N_NODES + TM - 1) / TM, 128, SMEM_BYTES>>>(nodes, w_ne, b_ne);
    k_edge_emb<<<(N_EDGES * 32 + 255) / 256, 256>>>(edges, w_ee, b_ee);

    // GNN layers
    for (int l = 0; l < 2; l++) {
        k_edge_fused<<<N_EDGES / TM, 128, SMEM_BYTES>>>(
            senders, receivers, epw + l * 3 * D * D, epb + l * D,
            emw + l * 2 * D * D, emb_ + l * 2 * D, elg + l * 2 * D, elb + l * 2 * D);
        k_agg<<<(N_NODES * 32 + 255) / 256, 256>>>();
        k_node_fused<<<(N_NODES + TM - 1) / TM, 128, SMEM_BYTES>>>(
            npw + l * 2 * D * D, npb + l * D,
            nmw + l * 2 * D * D, nmb + l * 2 * D, nlg + l * 2 * D, nlb + l * 2 * D);
    }

    // output head
    k_out<<<(N_NODES + TM - 1) / TM, 128, SMEM_BYTES>>>(ow, ob, og, obeta, pw, pb, out);
}

// round 3
// speedup vs baseline: 1.0929x; 1.0929x over previous
#include <cuda_runtime.h>
#include <math.h>

#define N_NODES 20000
#define N_EDGES 320000
#define D 128
#define KEMB 288
#define PRED 24
#define EPSV 1e-5f

#define TM 64
#define XS_STRIDE 132
#define SMEM_BYTES ((TM * XS_STRIDE + D * D) * 4)

typedef unsigned long long u64;

// ---------------- scratch (device globals; no runtime alloc allowed) ----------
__device__ float g_h[N_NODES * D];
__device__ float g_e[N_EDGES * D];
__device__ float g_agg[N_NODES * D];
__device__ float g_inv_cnt[N_NODES];
__device__ int   g_deg[N_NODES];
__device__ int   g_ptr[N_NODES + 1];
__device__ int   g_off[N_NODES];
__device__ int   g_idx[N_EDGES];

// ---------------- packed f32x2 helpers (FFMA2 path, sm_103a) -------------------
__device__ __forceinline__ u64 pack_dup(float x) {
    u64 r;
    asm("mov.b64 %0, {%1, %1};" : "=l"(r) : "f"(x));
    return r;
}
__device__ __forceinline__ void fma2(u64& d, u64 a, u64 b) {
    asm("fma.rn.f32x2 %0, %1, %2, %0;" : "+l"(d) : "l"(a), "l"(b));
}
__device__ __forceinline__ void unpack2(u64 v, float& lo, float& hi) {
    asm("mov.b64 {%0, %1}, %2;" : "=f"(lo), "=f"(hi) : "l"(v));
}

__device__ __forceinline__ void zero_acc2(u64 a2[8][4]) {
#pragma unroll
    for (int i = 0; i < 8; i++)
#pragma unroll
        for (int p = 0; p < 4; p++) a2[i][p] = 0ULL;
}

__device__ __forceinline__ void unpack_acc(const u64 a2[8][4], float acc[8][8]) {
#pragma unroll
    for (int i = 0; i < 8; i++)
#pragma unroll
        for (int p = 0; p < 4; p++) unpack2(a2[i][p], acc[i][2 * p], acc[i][2 * p + 1]);
}

// ---------------- helpers ------------------------------------------------------
__device__ __forceinline__ float gelu_f(float x) {
    // JAX approximate gelu: 0.5*x*(1+tanh(sqrt(2/pi)*(x+0.044715*x^3)))
    float u = 0.7978845608028654f * (x + 0.044715f * x * x * x);
    u = fminf(40.f, fmaxf(-40.f, u));
    float t = __expf(2.f * u);
    float th = __fdividef(t - 1.f, t + 1.f);
    return 0.5f * x * (1.f + th);
}

// stage W tile [rows x 128] from global into smem (rows*32 float4's)
__device__ __forceinline__ void stage_W(float* Ws, const float* __restrict__ src,
                                        int n4, int tid) {
    for (int idx = tid; idx < n4; idx += 128)
        ((float4*)Ws)[idx] = __ldg(((const float4*)src) + idx);
}

// stage 64 rows x 128 cols directly (row-aligned source)
__device__ __forceinline__ void stage_X_rows(float* Xs, const float* __restrict__ src,
                                             int row0, int M, int tid) {
    for (int idx = tid; idx < TM * 64; idx += 128) {
        int r = idx >> 6, c = idx & 63;
        int row = row0 + r;
        float2 v = make_float2(0.f, 0.f);
        if (row < M) v = __ldg(((const float2*)(src + (size_t)row * D)) + c);
        *(float2*)(Xs + r * XS_STRIDE + 2 * c) = v;
    }
}

// stage 64 rows x 128 cols gathered via index array
__device__ __forceinline__ void stage_X_gather(float* Xs, const float* __restrict__ src,
                                               const int* __restrict__ gidx,
                                               int row0, int M, int tid) {
    for (int idx = tid; idx < TM * 64; idx += 128) {
        int r = idx >> 6, c = idx & 63;
        int row = row0 + r;
        float2 v = make_float2(0.f, 0.f);
        if (row < M) {
            int g = __ldg(gidx + row);
            v = __ldg(((const float2*)(src + (size_t)g * D)) + c);
        }
        *(float2*)(Xs + r * XS_STRIDE + 2 * c) = v;
    }
}

// acc2 += Xs[64xK] * Ws[Kx128]  — packed f32x2 micro-kernel.
// 8x8 output per thread held as 8x4 f32x2 pairs; 128 threads = 8x16 grid.
// Per k: 2 amortized LDS.128 for a, 2 LDS.128 for b (pre-paired as u64x2),
// 8 dup-packs, 32 FFMA2 (= 64 FMAs).
__device__ __forceinline__ void gemm128_p2(const float* Xs, const float* Ws,
                                           u64 acc2[8][4], int K, int ty, int tx) {
    const float* xb = Xs + ty * 8 * XS_STRIDE;
    const float* wb = Ws + tx * 8;
#pragma unroll 2
    for (int k0 = 0; k0 < K; k0 += 4) {
        float4 av[8];
#pragma unroll
        for (int i = 0; i < 8; i++)
            av[i] = *(const float4*)(xb + i * XS_STRIDE + k0);
#pragma unroll
        for (int kk = 0; kk < 4; kk++) {
            const ulonglong2* w2 = (const ulonglong2*)(wb + (k0 + kk) * D);
            ulonglong2 b01 = w2[0];
            ulonglong2 b23 = w2[1];
#pragma unroll
            for (int i = 0; i < 8; i++) {
                float a = (kk == 0) ? av[i].x : (kk == 1) ? av[i].y
                        : (kk == 2) ? av[i].z : av[i].w;
                u64 ap = pack_dup(a);
                fma2(acc2[i][0], ap, b01.x);
                fma2(acc2[i][1], ap, b01.y);
                fma2(acc2[i][2], ap, b23.x);
                fma2(acc2[i][3], ap, b23.y);
            }
        }
    }
}

__device__ __forceinline__ void acc_to_X(float* Xs, const float acc[8][8], int ty, int tx) {
#pragma unroll
    for (int i = 0; i < 8; i++)
#pragma unroll
        for (int jp = 0; jp < 4; jp++)
            *(float2*)(Xs + (ty * 8 + i) * XS_STRIDE + tx * 8 + 2 * jp) =
                make_float2(acc[i][2 * jp], acc[i][2 * jp + 1]);
}

// bias + gelu + LayerNorm on acc (per-row reduction via shfl over the 16 tx lanes)
__device__ __forceinline__ void mlp_epilogue(float acc[8][8],
                                             const float* __restrict__ bias,
                                             const float* __restrict__ lg,
                                             const float* __restrict__ lb, int tx) {
    float bv[8], gv[8], bev[8];
#pragma unroll
    for (int j = 0; j < 8; j++) {
        bv[j] = __ldg(bias + tx * 8 + j);
        gv[j] = __ldg(lg + tx * 8 + j);
        bev[j] = __ldg(lb + tx * 8 + j);
    }
#pragma unroll
    for (int i = 0; i < 8; i++) {
        float s1 = 0.f, s2 = 0.f;
#pragma unroll
        for (int j = 0; j < 8; j++) {
            float z = gelu_f(acc[i][j] + bv[j]);
            acc[i][j] = z;
            s1 += z;
            s2 += z * z;
        }
#pragma unroll
        for (int o = 8; o >= 1; o >>= 1) {
            s1 += __shfl_xor_sync(0xffffffffu, s1, o);
            s2 += __shfl_xor_sync(0xffffffffu, s2, o);
        }
        float m = s1 * (1.f / D);
        float var = s2 * (1.f / D) - m * m;
        float rs = rsqrtf(var + EPSV);
#pragma unroll
        for (int j = 0; j < 8; j++)
            acc[i][j] = (acc[i][j] - m) * rs * gv[j] + bev[j];
    }
}

__device__ __forceinline__ void residual_store(float* dst, const float acc[8][8],
                                               int row0, int M, int ty, int tx) {
#pragma unroll
    for (int i = 0; i < 8; i++) {
        int row = row0 + ty * 8 + i;
        if (row < M) {
            float2* p = (float2*)(dst + (size_t)row * D + tx * 8);
#pragma unroll
            for (int jp = 0; jp < 4; jp++) {
                float2 v = p[jp];
                v.x += acc[i][2 * jp];
                v.y += acc[i][2 * jp + 1];
                p[jp] = v;
            }
        }
    }
}

__device__ __forceinline__ void plain_store(float* dst, const float acc[8][8],
                                            int row0, int M, int ty, int tx) {
#pragma unroll
    for (int i = 0; i < 8; i++) {
        int row = row0 + ty * 8 + i;
        if (row < M) {
            float2* p = (float2*)(dst + (size_t)row * D + tx * 8);
#pragma unroll
            for (int jp = 0; jp < 4; jp++)
                p[jp] = make_float2(acc[i][2 * jp], acc[i][2 * jp + 1]);
        }
    }
}

// ---------------- CSR construction --------------------------------------------
__global__ void k_zero_deg() {
    int i = blockIdx.x * blockDim.x + threadIdx.x;
    if (i < N_NODES) g_deg[i] = 0;
}

__global__ void k_hist(const int* __restrict__ recv) {
    int i = blockIdx.x * blockDim.x + threadIdx.x;
    if (i < N_EDGES) atomicAdd(&g_deg[recv[i]], 1);
}

__global__ void k_scan() {  // single block, 1024 threads
    __shared__ int partial[1024];
    const int CH = (N_NODES + 1023) / 1024;
    int t = threadIdx.x;
    int start = t * CH;
    int end = min(start + CH, N_NODES);
    int s = 0;
    for (int i = start; i < end; i++) s += g_deg[i];
    partial[t] = s;
    __syncthreads();
    for (int o = 1; o < 1024; o <<= 1) {
        int v = (t >= o) ? partial[t - o] : 0;
        __syncthreads();
        partial[t] += v;
        __syncthreads();
    }
    int run = partial[t] - s;  // exclusive prefix
    for (int i = start; i < end; i++) {
        int d = g_deg[i];
        g_ptr[i] = run;
        g_off[i] = run;
        g_inv_cnt[i] = 1.0f / (float)max(d, 1);
        run += d;
    }
    if (t == 0) g_ptr[N_NODES] = N_EDGES;
}

__global__ void k_scatter(const int* __restrict__ recv) {
    int i = blockIdx.x * blockDim.x + threadIdx.x;
    if (i < N_EDGES) {
        int p = atomicAdd(&g_off[recv[i]], 1);
        g_idx[p] = i;
    }
}

__global__ void k_sortlists() {  // deterministic order within each node's list
    int n = blockIdx.x * blockDim.x + threadIdx.x;
    if (n >= N_NODES) return;
    int b = g_ptr[n], e2 = g_ptr[n + 1];
    for (int i = b + 1; i < e2; i++) {
        int v = g_idx[i];
        int j = i - 1;
        while (j >= b && g_idx[j] > v) {
            g_idx[j + 1] = g_idx[j];
            j--;
        }
        g_idx[j + 1] = v;
    }
}

// ---------------- embeddings ---------------------------------------------------
__global__ void __launch_bounds__(128, 2) k_node_emb(const float* __restrict__ nodes,
                                                     const float* __restrict__ w,
                                                     const float* __restrict__ b) {
    extern __shared__ float sm[];
    float* Xs = sm;
    float* Ws = sm + TM * XS_STRIDE;
    int tid = threadIdx.x, ty = tid >> 4, tx = tid & 15;
    int row0 = blockIdx.x * TM;
    u64 acc2[8][4];
    zero_acc2(acc2);
    for (int s = 0; s < 3; s++) {  // K = 288 in 3 chunks of 96
        __syncthreads();
        for (int idx = tid; idx < TM * 48; idx += 128) {
            int r = idx / 48, c = idx % 48;
            int row = row0 + r;
            float2 v = make_float2(0.f, 0.f);
            if (row < N_NODES)
                v = __ldg(((const float2*)(nodes + (size_t)row * KEMB + s * 96)) + c);
            *(float2*)(Xs + r * XS_STRIDE + 2 * c) = v;
        }
        stage_W(Ws, w + s * 96 * D, 96 * 32, tid);
        __syncthreads();
        gemm128_p2(Xs, Ws, acc2, 96, ty, tx);
    }
    float acc[8][8];
    unpack_acc(acc2, acc);
    float bv[8];
#pragma unroll
    for (int j = 0; j < 8; j++) bv[j] = __ldg(b + tx * 8 + j);
#pragma unroll
    for (int i = 0; i < 8; i++)
#pragma unroll
        for (int j = 0; j < 8; j++) acc[i][j] += bv[j];
    plain_store(g_h, acc, row0, N_NODES, ty, tx);
}

__global__ void k_edge_emb(const float* __restrict__ edges,
                           const float* __restrict__ w, const float* __restrict__ b) {
    int idx = blockIdx.x * blockDim.x + threadIdx.x;
    if (idx >= N_EDGES * 32) return;
    int ei = idx >> 5, c4 = idx & 31;
    float e0 = __ldg(edges + ei * 2);
    float e1 = __ldg(edges + ei * 2 + 1);
    float4 w0 = __ldg(((const float4*)w) + c4);
    float4 w1 = __ldg(((const float4*)(w + D)) + c4);
    float4 bb = __ldg(((const float4*)b) + c4);
    float4 r;
    r.x = e0 * w0.x + e1 * w1.x + bb.x;
    r.y = e0 * w0.y + e1 * w1.y + bb.y;
    r.z = e0 * w0.z + e1 * w1.z + bb.z;
    r.w = e0 * w0.w + e1 * w1.w + bb.w;
    ((float4*)(g_e + (size_t)ei * D))[c4] = r;
}

// ---------------- fused edge update -------------------------------------------
__global__ void __launch_bounds__(128, 2) k_edge_fused(
    const int* __restrict__ senders, const int* __restrict__ receivers,
    const float* __restrict__ pw, const float* __restrict__ pb,
    const float* __restrict__ mw, const float* __restrict__ mb,
    const float* __restrict__ lg, const float* __restrict__ lb) {
    extern __shared__ float sm[];
    float* Xs = sm;
    float* Ws = sm + TM * XS_STRIDE;
    int tid = threadIdx.x, ty = tid >> 4, tx = tid & 15;
    int row0 = blockIdx.x * TM;
    u64 acc2[8][4];
    zero_acc2(acc2);
    // proj: K=384 in 3 chunks (e, h[senders], h[receivers])
    for (int s = 0; s < 3; s++) {
        __syncthreads();
        if (s == 0)
            stage_X_rows(Xs, g_e, row0, N_EDGES, tid);
        else
            stage_X_gather(Xs, g_h, (s == 1) ? senders : receivers, row0, N_EDGES, tid);
        stage_W(Ws, pw + s * 128 * D, 128 * 32, tid);
        __syncthreads();
        gemm128_p2(Xs, Ws, acc2, 128, ty, tx);
    }
    float acc[8][8];
    unpack_acc(acc2, acc);
    {
        float bv[8];
#pragma unroll
        for (int j = 0; j < 8; j++) bv[j] = __ldg(pb + tx * 8 + j);
#pragma unroll
        for (int i = 0; i < 8; i++)
#pragma unroll
            for (int j = 0; j < 8; j++) acc[i][j] += bv[j];
    }
    // MLP x2: LN(gelu(x@W + b))
    for (int m = 0; m < 2; m++) {
        __syncthreads();
        acc_to_X(Xs, acc, ty, tx);
        stage_W(Ws, mw + m * D * D, 128 * 32, tid);
        __syncthreads();
        zero_acc2(acc2);
        gemm128_p2(Xs, Ws, acc2, 128, ty, tx);
        unpack_acc(acc2, acc);
        mlp_epilogue(acc, mb + m * D, lg + m * D, lb + m * D, tx);
    }
    residual_store(g_e, acc, row0, N_EDGES, ty, tx);
}

// ---------------- scatter-mean aggregation (pull via CSR) ----------------------
__global__ void __launch_bounds__(256) k_agg() {
    int warp = (blockIdx.x * 256 + threadIdx.x) >> 5;
    int lane = threadIdx.x & 31;
    if (warp >= N_NODES) return;
    int b = g_ptr[warp], e2 = g_ptr[warp + 1];
    float4 a = make_float4(0.f, 0.f, 0.f, 0.f);
    for (int p = b; p < e2; p++) {
        int ei = g_idx[p];
        float4 v = *(const float4*)(g_e + (size_t)ei * D + lane * 4);
        a.x += v.x; a.y += v.y; a.z += v.z; a.w += v.w;
    }
    float ic = g_inv_cnt[warp];
    *(float4*)(g_agg + (size_t)warp * D + lane * 4) =
        make_float4(a.x * ic, a.y * ic, a.z * ic, a.w * ic);
}

// ---------------- fused node update -------------------------------------------
__global__ void __launch_bounds__(128, 2) k_node_fused(
    const float* __restrict__ pw, const float* __restrict__ pb,
    const float* __restrict__ mw, const float* __restrict__ mb,
    const float* __restrict__ lg, const float* __restrict__ lb) {
    extern __shared__ float sm[];
    float* Xs = sm;
    float* Ws = sm + TM * XS_STRIDE;
    int tid = threadIdx.x, ty = tid >> 4, tx = tid & 15;
    int row0 = blockIdx.x * TM;
    u64 acc2[8][4];
    zero_acc2(acc2);
    for (int s = 0; s < 2; s++) {  // K=256: [h, agg]
        __syncthreads();
        stage_X_rows(Xs, (s == 0) ? g_h : g_agg, row0, N_NODES, tid);
        stage_W(Ws, pw + s * 128 * D, 128 * 32, tid);
        __syncthreads();
        gemm128_p2(Xs, Ws, acc2, 128, ty, tx);
    }
    float acc[8][8];
    unpack_acc(acc2, acc);
    {
        float bv[8];
#pragma unroll
        for (int j = 0; j < 8; j++) bv[j] = __ldg(pb + tx * 8 + j);
#pragma unroll
        for (int i = 0; i < 8; i++)
#pragma unroll
            for (int j = 0; j < 8; j++) acc[i][j] += bv[j];
    }
    for (int m = 0; m < 2; m++) {
        __syncthreads();
        acc_to_X(Xs, acc, ty, tx);
        stage_W(Ws, mw + m * D * D, 128 * 32, tid);
        __syncthreads();
        zero_acc2(acc2);
        gemm128_p2(Xs, Ws, acc2, 128, ty, tx);
        unpack_acc(acc2, acc);
        mlp_epilogue(acc, mb + m * D, lg + m * D, lb + m * D, tx);
    }
    residual_store(g_h, acc, row0, N_NODES, ty, tx);
}

// ---------------- output head --------------------------------------------------
__global__ void __launch_bounds__(128, 2) k_out(
    const float* __restrict__ w1, const float* __restrict__ b1,
    const float* __restrict__ lg, const float* __restrict__ lb,
    const float* __restrict__ pw, const float* __restrict__ pb,
    float* __restrict__ out) {
    extern __shared__ float sm[];
    float* Xs = sm;
    float* Ws = sm + TM * XS_STRIDE;
    int tid = threadIdx.x, ty = tid >> 4, tx = tid & 15;
    int row0 = blockIdx.x * TM;
    u64 acc2[8][4];
    zero_acc2(acc2);
    stage_X_rows(Xs, g_h, row0, N_NODES, tid);
    stage_W(Ws, w1, 128 * 32, tid);
    __syncthreads();
    gemm128_p2(Xs, Ws, acc2, 128, ty, tx);
    float acc[8][8];
    unpack_acc(acc2, acc);
    mlp_epilogue(acc, b1, lg, lb, tx);
    __syncthreads();
    acc_to_X(Xs, acc, ty, tx);
    stage_W(Ws, pw, (D * PRED) / 4, tid);  // 128x24 proj weights
    __syncthreads();
    for (int idx = tid; idx < TM * PRED; idx += 128) {
        int r = idx / PRED, p = idx % PRED;
        int row = row0 + r;
        if (row < N_NODES) {
            float s = __ldg(pb + p);
            const float* xr = Xs + r * XS_STRIDE;
#pragma unroll 4
            for (int k = 0; k < D; k++) s += xr[k] * Ws[k * PRED + p];
            out[(size_t)row * PRED + p] = s;
        }
    }
}

// ---------------- launch -------------------------------------------------------
extern "C" void kernel_launch(void* const* d_in, const int* in_sizes, int n_in,
                              void* d_out, int out_size) {
    const float* nodes = (const float*)d_in[0];
    const float* edges = (const float*)d_in[1];
    const int* senders = (const int*)d_in[2];
    const int* receivers = (const int*)d_in[3];
    const float* w_ne = (const float*)d_in[4];
    const float* b_ne = (const float*)d_in[5];
    const float* w_ee = (const float*)d_in[6];
    const float* b_ee = (const float*)d_in[7];
    const float* epw = (const float*)d_in[8];
    const float* epb = (const float*)d_in[9];
    const float* npw = (const float*)d_in[10];
    const float* npb = (const float*)d_in[11];
    const float* emw = (const float*)d_in[12];
    const float* emb_ = (const float*)d_in[13];
    const float* elg = (const float*)d_in[14];
    const float* elb = (const float*)d_in[15];
    const float* nmw = (const float*)d_in[16];
    const float* nmb = (const float*)d_in[17];
    const float* nlg = (const float*)d_in[18];
    const float* nlb = (const float*)d_in[19];
    const float* ow = (const float*)d_in[20];
    const float* ob = (const float*)d_in[21];
    const float* og = (const float*)d_in[22];
    const float* obeta = (const float*)d_in[23];
    const float* pw = (const float*)d_in[24];
    const float* pb = (const float*)d_in[25];
    float* out = (float*)d_out;

    cudaFuncSetAttribute(k_edge_fused, cudaFuncAttributeMaxDynamicSharedMemorySize, SMEM_BYTES);
    cudaFuncSetAttribute(k_node_fused, cudaFuncAttributeMaxDynamicSharedMemorySize, SMEM_BYTES);
    cudaFuncSetAttribute(k_node_emb, cudaFuncAttributeMaxDynamicSharedMemorySize, SMEM_BYTES);
    cudaFuncSetAttribute(k_out, cudaFuncAttributeMaxDynamicSharedMemorySize, SMEM_BYTES);

    // CSR build (deterministic: per-node lists sorted by edge id)
    k_zero_deg<<<(N_NODES + 255) / 256, 256>>>();
    k_hist<<<(N_EDGES + 255) / 256, 256>>>(receivers);
    k_scan<<<1, 1024>>>();
    k_scatter<<<(N_EDGES + 255) / 256, 256>>>(receivers);
    k_sortlists<<<(N_NODES + 255) / 256, 256>>>();

    // embeddings
    k_node_emb<<<(N_NODES + TM - 1) / TM, 128, SMEM_BYTES>>>(nodes, w_ne, b_ne);
    k_edge_emb<<<(N_EDGES * 32 + 255) / 256, 256>>>(edges, w_ee, b_ee);

    // GNN layers
    for (int l = 0; l < 2; l++) {
        k_edge_fused<<<N_EDGES / TM, 128, SMEM_BYTES>>>(
            senders, receivers, epw + l * 3 * D * D, epb + l * D,
            emw + l * 2 * D * D, emb_ + l * 2 * D, elg + l * 2 * D, elb + l * 2 * D);
        k_agg<<<(N_NODES * 32 + 255) / 256, 256>>>();
        k_node_fused<<<(N_NODES + TM - 1) / TM, 128, SMEM_BYTES>>>(
            npw + l * 2 * D * D, npb + l * D,
            nmw + l * 2 * D * D, nmb + l * 2 * D, nlg + l * 2 * D, nlb + l * 2 * D);
    }

    // output head
    k_out<<<(N_NODES + TM - 1) / TM, 128, SMEM_BYTES>>>(ow, ob, og, obeta, pw, pb, out);
}

// round 6
// speedup vs baseline: 1.1697x; 1.0702x over previous
#include <cuda_runtime.h>
#include <cuda_bf16.h>
#include <math.h>
#include <stdint.h>

#define N_NODES 20000
#define N_EDGES 320000
#define D 128
#define KEMB 288
#define PRED 24
#define EPSV 1e-5f

typedef unsigned long long u64;

// ---------------- scratch (device globals; no runtime alloc allowed) ----------
__device__ float g_h[N_NODES * D];
__device__ float g_e[N_EDGES * D];
__device__ float g_agg[N_NODES * D];
__device__ float g_inv_cnt[N_NODES];
__device__ int   g_deg[N_NODES];
__device__ int   g_ptr[N_NODES + 1];
__device__ int   g_off[N_NODES];
__device__ int   g_idx[N_EDGES];

// =====================================================================
// portable tensor-core path: ldmatrix + mma.sync (bf16, fp32 accum)
// =====================================================================
#define AST 136                      // bf16 row stride: 272B == 16 mod 128 -> conflict-free ldmatrix
#define TILE_BYTES (128 * AST * 2)   // 34816
#define TS_AHI 0
#define TS_ALO (TILE_BYTES)
#define TS_BHI (2 * TILE_BYTES)
#define TS_BLO (3 * TILE_BYTES)
#define TS_BYTES (4 * TILE_BYTES)    // 139264

__device__ __forceinline__ uint32_t smem_to_u32(const void* smem_ptr) {
    uint32_t addr;
    asm("{ .reg .u64 tmp; cvta.to.shared.u64 tmp, %1; cvt.u32.u64 %0, tmp; }"
        : "=r"(addr) : "l"(smem_ptr));
    return addr;
}

__device__ __forceinline__ void ldsm4(uint32_t r[4], uint32_t addr) {
    asm volatile("ldmatrix.sync.aligned.m8n8.x4.shared.b16 {%0,%1,%2,%3}, [%4];"
                 : "=r"(r[0]), "=r"(r[1]), "=r"(r[2]), "=r"(r[3]) : "r"(addr));
}

__device__ __forceinline__ void mma_bf16(float d[4], const uint32_t a[4],
                                         uint32_t b0, uint32_t b1) {
    asm volatile(
        "mma.sync.aligned.m16n8k16.row.col.f32.bf16.bf16.f32 "
        "{%0,%1,%2,%3}, {%4,%5,%6,%7}, {%8,%9}, {%0,%1,%2,%3};"
        : "+f"(d[0]), "+f"(d[1]), "+f"(d[2]), "+f"(d[3])
        : "r"(a[0]), "r"(a[1]), "r"(a[2]), "r"(a[3]), "r"(b0), "r"(b1));
}

// A-fragment address (16x16 tile at m0,k0), per-lane
__device__ __forceinline__ uint32_t addrA(uint32_t base, int m0, int k0, int lane) {
    int r = m0 + (lane & 15);
    int c = k0 + ((lane >> 4) << 3);
    return base + (uint32_t)(r * AST + c) * 2;
}
// B-fragment address over transposed-stored W (rows = n, cols = k): two n8 tiles
__device__ __forceinline__ uint32_t addrB(uint32_t base, int n0, int k0, int lane) {
    int r = n0 + (lane & 7) + ((lane & 16) ? 8 : 0);
    int c = k0 + ((lane & 8) ? 8 : 0);
    return base + (uint32_t)(r * AST + c) * 2;
}

// pack two floats into bf16x2 (first arg -> low half)
__device__ __forceinline__ uint32_t pack_bf16(float lo, float hi) {
    uint32_t r;
    asm("cvt.rn.bf16x2.f32 %0, %1, %2;" : "=r"(r) : "f"(hi), "f"(lo));
    return r;
}
// hi/lo split of a pair: hi = bf16(x), lo = bf16(x - float(hi))
__device__ __forceinline__ void split_pair(float a, float b, uint32_t& hi, uint32_t& lo) {
    float ah = __bfloat162float(__float2bfloat16(a));
    float bh = __bfloat162float(__float2bfloat16(b));
    hi = pack_bf16(a, b);
    lo = pack_bf16(a - ah, b - bh);
}

__device__ __forceinline__ float gelu_f(float x) {
    float u = 0.7978845608028654f * (x + 0.044715f * x * x * x);
    u = fminf(40.f, fmaxf(-40.f, u));
    float t = __expf(2.f * u);
    float th = __fdividef(t - 1.f, t + 1.f);
    return 0.5f * x * (1.f + th);
}

// stage X tile [128 rows x 128 cols fp32] -> A_hi/A_lo bf16 (optionally gathered)
__device__ __forceinline__ void stage_X(char* Ahi, char* Alo, const float* __restrict__ src,
                                        const int* __restrict__ gidx, int row0, int Mlim,
                                        int tid) {
    for (int it = tid; it < 128 * 32; it += 256) {
        int r = it >> 5, c4 = it & 31, k = c4 * 4;
        int row = row0 + r;
        float4 v = make_float4(0.f, 0.f, 0.f, 0.f);
        if (row < Mlim) {
            int sr = gidx ? __ldg(gidx + row) : row;
            v = __ldg(((const float4*)(src + (size_t)sr * D)) + c4);
        }
        uint32_t h0, l0, h1, l1;
        split_pair(v.x, v.y, h0, l0);
        split_pair(v.z, v.w, h1, l1);
        uint32_t off = (uint32_t)(r * AST + k) * 2;
        *(uint2*)(Ahi + off) = make_uint2(h0, h1);
        *(uint2*)(Alo + off) = make_uint2(l0, l1);
    }
}

// stage W [128k x 128c fp32, row-major] transposed -> Bt_hi/Bt_lo [c][k] bf16
__device__ __forceinline__ void stage_Wt(char* Bhi, char* Blo, const float* __restrict__ w,
                                         int tid) {
    for (int it = tid; it < 64 * 32; it += 256) {
        int kp = it >> 5, c4 = it & 31;
        int k = 2 * kp, c = 4 * c4;
        float4 w0 = __ldg(((const float4*)(w + (size_t)k * D)) + c4);
        float4 w1 = __ldg(((const float4*)(w + (size_t)(k + 1) * D)) + c4);
        float a0[4] = {w0.x, w0.y, w0.z, w0.w};
        float a1[4] = {w1.x, w1.y, w1.z, w1.w};
#pragma unroll
        for (int u = 0; u < 4; u++) {
            uint32_t hi, lo;
            split_pair(a0[u], a1[u], hi, lo);
            uint32_t off = (uint32_t)((c + u) * AST + k) * 2;
            *(uint32_t*)(Bhi + off) = hi;
            *(uint32_t*)(Blo + off) = lo;
        }
    }
}

// acc += X[warp-rows 16 x 128] @ W[128 x 128] with 3-product bf16 split.
// acc[nt][..]: nt-th n8 tile; d0,d1 row lane/4; d2,d3 row lane/4+8.
__device__ __forceinline__ void gemm_mma(uint32_t sb, float acc[16][4], int warp, int lane) {
    int m0 = warp * 16;
    uint32_t ahi = sb + TS_AHI, alo = sb + TS_ALO;
    uint32_t bhi = sb + TS_BHI, blo = sb + TS_BLO;
#pragma unroll
    for (int ks = 0; ks < 8; ks++) {
        int k0 = ks * 16;
        uint32_t ah[4], al[4];
        ldsm4(ah, addrA(ahi, m0, k0, lane));
        ldsm4(al, addrA(alo, m0, k0, lane));
#pragma unroll
        for (int nb = 0; nb < 8; nb++) {
            int n0 = nb * 16;
            uint32_t bh[4], bl[4];
            ldsm4(bh, addrB(bhi, n0, k0, lane));
            ldsm4(bl, addrB(blo, n0, k0, lane));
            mma_bf16(acc[2 * nb],     ah, bh[0], bh[1]);
            mma_bf16(acc[2 * nb],     ah, bl[0], bl[1]);
            mma_bf16(acc[2 * nb],     al, bh[0], bh[1]);
            mma_bf16(acc[2 * nb + 1], ah, bh[2], bh[3]);
            mma_bf16(acc[2 * nb + 1], ah, bl[2], bl[3]);
            mma_bf16(acc[2 * nb + 1], al, bh[2], bh[3]);
        }
    }
}

__device__ __forceinline__ void zero_acc16(float acc[16][4]) {
#pragma unroll
    for (int i = 0; i < 16; i++)
#pragma unroll
        for (int j = 0; j < 4; j++) acc[i][j] = 0.f;
}

// proj epilogue: acc + bias -> A_hi/A_lo (no activation)
__device__ __forceinline__ void epi_proj_mma(float acc[16][4], const float* __restrict__ pb,
                                             char* Ahi, char* Alo, int warp, int lane) {
    int rb = warp * 16 + (lane >> 2);
    int cb = 2 * (lane & 3);
#pragma unroll
    for (int half = 0; half < 2; half++) {
        int row = rb + half * 8;
#pragma unroll
        for (int nt = 0; nt < 16; nt++) {
            int col = nt * 8 + cb;
            float x = acc[nt][half * 2]     + __ldg(pb + col);
            float y = acc[nt][half * 2 + 1] + __ldg(pb + col + 1);
            uint32_t hi, lo;
            split_pair(x, y, hi, lo);
            uint32_t off = (uint32_t)(row * AST + col) * 2;
            *(uint32_t*)(Ahi + off) = hi;
            *(uint32_t*)(Alo + off) = lo;
        }
    }
}

// MLP epilogue: y = LN(gelu(acc + bias)). toA: write A_hi/A_lo; else residual-add to global.
__device__ __forceinline__ void epi_ln_mma(float acc[16][4], const float* __restrict__ bias,
                                           const float* __restrict__ lg,
                                           const float* __restrict__ lb,
                                           bool toA, char* Ahi, char* Alo,
                                           float* __restrict__ dst, int row0, int Mlim,
                                           int warp, int lane) {
    int rb = warp * 16 + (lane >> 2);
    int cb = 2 * (lane & 3);
#pragma unroll
    for (int half = 0; half < 2; half++) {
        int row = rb + half * 8;
        float s1 = 0.f, s2 = 0.f;
#pragma unroll
        for (int nt = 0; nt < 16; nt++) {
            int col = nt * 8 + cb;
            float z0 = gelu_f(acc[nt][half * 2]     + __ldg(bias + col));
            float z1 = gelu_f(acc[nt][half * 2 + 1] + __ldg(bias + col + 1));
            acc[nt][half * 2] = z0;           // reuse acc slots for z
            acc[nt][half * 2 + 1] = z1;
            s1 += z0 + z1;
            s2 += z0 * z0 + z1 * z1;
        }
        s1 += __shfl_xor_sync(0xffffffffu, s1, 1);
        s2 += __shfl_xor_sync(0xffffffffu, s2, 1);
        s1 += __shfl_xor_sync(0xffffffffu, s1, 2);
        s2 += __shfl_xor_sync(0xffffffffu, s2, 2);
        float m = s1 * (1.f / D);
        float var = s2 * (1.f / D) - m * m;
        float rs = rsqrtf(var + EPSV);
#pragma unroll
        for (int nt = 0; nt < 16; nt++) {
            int col = nt * 8 + cb;
            float y0 = (acc[nt][half * 2]     - m) * rs * __ldg(lg + col)     + __ldg(lb + col);
            float y1 = (acc[nt][half * 2 + 1] - m) * rs * __ldg(lg + col + 1) + __ldg(lb + col + 1);
            if (toA) {
                uint32_t hi, lo;
                split_pair(y0, y1, hi, lo);
                uint32_t off = (uint32_t)(row * AST + col) * 2;
                *(uint32_t*)(Ahi + off) = hi;
                *(uint32_t*)(Alo + off) = lo;
            } else if (row0 + row < Mlim) {
                float2* p = (float2*)(dst + (size_t)(row0 + row) * D + col);
                float2 v = *p;
                v.x += y0;
                v.y += y1;
                *p = v;
            }
        }
    }
}

// fused tile: proj (nchunks x K=128) + 2x MLP(LN(gelu)) + residual, on HMMA
__device__ void fused_tile(char* smem, int row0, int Mlim,
                           const float* x0, const int* gi0,
                           const float* x1, const int* gi1,
                           const float* x2, const int* gi2, int nchunks,
                           const float* pw, const float* pb,
                           const float* mw, const float* mb,
                           const float* lg, const float* lb,
                           float* resid_dst) {
    uint32_t sb = smem_to_u32(smem);
    int tid = threadIdx.x, lane = tid & 31, warp = tid >> 5;
    float acc[16][4];
    zero_acc16(acc);

    // --- projection: accumulate nchunks K=128 pieces ---
    for (int c = 0; c < nchunks; c++) {
        const float* xs = (c == 0) ? x0 : (c == 1) ? x1 : x2;
        const int* gi = (c == 0) ? gi0 : (c == 1) ? gi1 : gi2;
        stage_X(smem + TS_AHI, smem + TS_ALO, xs, gi, row0, Mlim, tid);
        stage_Wt(smem + TS_BHI, smem + TS_BLO, pw + (size_t)c * D * D, tid);
        __syncthreads();
        gemm_mma(sb, acc, warp, lane);
        __syncthreads();
    }
    epi_proj_mma(acc, pb, smem + TS_AHI, smem + TS_ALO, warp, lane);

    // --- 2x MLP: LN(gelu(X@W + b)); last adds residual & stores ---
    for (int m = 0; m < 2; m++) {
        stage_Wt(smem + TS_BHI, smem + TS_BLO, mw + (size_t)m * D * D, tid);
        __syncthreads();
        zero_acc16(acc);
        gemm_mma(sb, acc, warp, lane);
        __syncthreads();
        if (m == 0)
            epi_ln_mma(acc, mb, lg, lb, true, smem + TS_AHI, smem + TS_ALO,
                       nullptr, 0, 0, warp, lane);
        else
            epi_ln_mma(acc, mb + D, lg + D, lb + D, false, nullptr, nullptr,
                       resid_dst, row0, Mlim, warp, lane);
    }
}

__global__ void __launch_bounds__(256, 1) k_edge_t(
    const int* __restrict__ senders, const int* __restrict__ receivers,
    const float* __restrict__ pw, const float* __restrict__ pb,
    const float* __restrict__ mw, const float* __restrict__ mb,
    const float* __restrict__ lg, const float* __restrict__ lb) {
    extern __shared__ char smem[];
    fused_tile(smem, blockIdx.x * 128, N_EDGES,
               g_e, nullptr, g_h, senders, g_h, receivers, 3,
               pw, pb, mw, mb, lg, lb, g_e);
}

__global__ void __launch_bounds__(256, 1) k_node_t(
    const float* __restrict__ pw, const float* __restrict__ pb,
    const float* __restrict__ mw, const float* __restrict__ mb,
    const float* __restrict__ lg, const float* __restrict__ lb) {
    extern __shared__ char smem[];
    fused_tile(smem, blockIdx.x * 128, N_NODES,
               g_h, nullptr, g_agg, nullptr, nullptr, nullptr, 2,
               pw, pb, mw, mb, lg, lb, g_h);
}

// =====================================================================
// scalar FFMA2 path (embeddings / output head) — from R2
// =====================================================================
#define TM 64
#define XS_STRIDE 132
#define SMEM_BYTES ((TM * XS_STRIDE + D * D) * 4)

__device__ __forceinline__ u64 pack_dup(float x) {
    u64 r;
    asm("mov.b64 %0, {%1, %1};" : "=l"(r) : "f"(x));
    return r;
}
__device__ __forceinline__ void fma2(u64& d, u64 a, u64 b) {
    asm("fma.rn.f32x2 %0, %1, %2, %0;" : "+l"(d) : "l"(a), "l"(b));
}
__device__ __forceinline__ void unpack2(u64 v, float& lo, float& hi) {
    asm("mov.b64 {%0, %1}, %2;" : "=f"(lo), "=f"(hi) : "l"(v));
}
__device__ __forceinline__ void zero_acc2(u64 a2[8][4]) {
#pragma unroll
    for (int i = 0; i < 8; i++)
#pragma unroll
        for (int p = 0; p < 4; p++) a2[i][p] = 0ULL;
}
__device__ __forceinline__ void unpack_acc(const u64 a2[8][4], float acc[8][8]) {
#pragma unroll
    for (int i = 0; i < 8; i++)
#pragma unroll
        for (int p = 0; p < 4; p++) unpack2(a2[i][p], acc[i][2 * p], acc[i][2 * p + 1]);
}
__device__ __forceinline__ void stage_W(float* Ws, const float* __restrict__ src, int n4, int tid) {
    for (int idx = tid; idx < n4; idx += 128)
        ((float4*)Ws)[idx] = __ldg(((const float4*)src) + idx);
}
__device__ __forceinline__ void stage_X_rows(float* Xs, const float* __restrict__ src,
                                             int row0, int M, int tid) {
    for (int idx = tid; idx < TM * 64; idx += 128) {
        int r = idx >> 6, c = idx & 63;
        int row = row0 + r;
        float2 v = make_float2(0.f, 0.f);
        if (row < M) v = __ldg(((const float2*)(src + (size_t)row * D)) + c);
        *(float2*)(Xs + r * XS_STRIDE + 2 * c) = v;
    }
}
__device__ __forceinline__ void gemm128_p2(const float* Xs, const float* Ws,
                                           u64 acc2[8][4], int K, int ty, int tx) {
    const float* xb = Xs + ty * 8 * XS_STRIDE;
    const float* wb = Ws + tx * 8;
#pragma unroll 2
    for (int k0 = 0; k0 < K; k0 += 4) {
        float4 av[8];
#pragma unroll
        for (int i = 0; i < 8; i++)
            av[i] = *(const float4*)(xb + i * XS_STRIDE + k0);
#pragma unroll
        for (int kk = 0; kk < 4; kk++) {
            const ulonglong2* w2 = (const ulonglong2*)(wb + (k0 + kk) * D);
            ulonglong2 b01 = w2[0];
            ulonglong2 b23 = w2[1];
#pragma unroll
            for (int i = 0; i < 8; i++) {
                float a = (kk == 0) ? av[i].x : (kk == 1) ? av[i].y
                        : (kk == 2) ? av[i].z : av[i].w;
                u64 ap = pack_dup(a);
                fma2(acc2[i][0], ap, b01.x);
                fma2(acc2[i][1], ap, b01.y);
                fma2(acc2[i][2], ap, b23.x);
                fma2(acc2[i][3], ap, b23.y);
            }
        }
    }
}
__device__ __forceinline__ void acc_to_X(float* Xs, const float acc[8][8], int ty, int tx) {
#pragma unroll
    for (int i = 0; i < 8; i++)
#pragma unroll
        for (int jp = 0; jp < 4; jp++)
            *(float2*)(Xs + (ty * 8 + i) * XS_STRIDE + tx * 8 + 2 * jp) =
                make_float2(acc[i][2 * jp], acc[i][2 * jp + 1]);
}
__device__ __forceinline__ void mlp_epilogue(float acc[8][8],
                                             const float* __restrict__ bias,
                                             const float* __restrict__ lg,
                                             const float* __restrict__ lb, int tx) {
    float bv[8], gv[8], bev[8];
#pragma unroll
    for (int j = 0; j < 8; j++) {
        bv[j] = __ldg(bias + tx * 8 + j);
        gv[j] = __ldg(lg + tx * 8 + j);
        bev[j] = __ldg(lb + tx * 8 + j);
    }
#pragma unroll
    for (int i = 0; i < 8; i++) {
        float s1 = 0.f, s2 = 0.f;
#pragma unroll
        for (int j = 0; j < 8; j++) {
            float z = gelu_f(acc[i][j] + bv[j]);
            acc[i][j] = z;
            s1 += z;
            s2 += z * z;
        }
#pragma unroll
        for (int o = 8; o >= 1; o >>= 1) {
            s1 += __shfl_xor_sync(0xffffffffu, s1, o);
            s2 += __shfl_xor_sync(0xffffffffu, s2, o);
        }
        float m = s1 * (1.f / D);
        float var = s2 * (1.f / D) - m * m;
        float rs = rsqrtf(var + EPSV);
#pragma unroll
        for (int j = 0; j < 8; j++)
            acc[i][j] = (acc[i][j] - m) * rs * gv[j] + bev[j];
    }
}
__device__ __forceinline__ void plain_store(float* dst, const float acc[8][8],
                                            int row0, int M, int ty, int tx) {
#pragma unroll
    for (int i = 0; i < 8; i++) {
        int row = row0 + ty * 8 + i;
        if (row < M) {
            float2* p = (float2*)(dst + (size_t)row * D + tx * 8);
#pragma unroll
            for (int jp = 0; jp < 4; jp++)
                p[jp] = make_float2(acc[i][2 * jp], acc[i][2 * jp + 1]);
        }
    }
}

// ---------------- CSR construction --------------------------------------------
__global__ void k_zero_deg() {
    int i = blockIdx.x * blockDim.x + threadIdx.x;
    if (i < N_NODES) g_deg[i] = 0;
}
__global__ void k_hist(const int* __restrict__ recv) {
    int i = blockIdx.x * blockDim.x + threadIdx.x;
    if (i < N_EDGES) atomicAdd(&g_deg[recv[i]], 1);
}
__global__ void k_scan() {
    __shared__ int partial[1024];
    const int CH = (N_NODES + 1023) / 1024;
    int t = threadIdx.x;
    int start = t * CH;
    int end = min(start + CH, N_NODES);
    int s = 0;
    for (int i = start; i < end; i++) s += g_deg[i];
    partial[t] = s;
    __syncthreads();
    for (int o = 1; o < 1024; o <<= 1) {
        int v = (t >= o) ? partial[t - o] : 0;
        __syncthreads();
        partial[t] += v;
        __syncthreads();
    }
    int run = partial[t] - s;
    for (int i = start; i < end; i++) {
        int d = g_deg[i];
        g_ptr[i] = run;
        g_off[i] = run;
        g_inv_cnt[i] = 1.0f / (float)max(d, 1);
        run += d;
    }
    if (t == 0) g_ptr[N_NODES] = N_EDGES;
}
__global__ void k_scatter(const int* __restrict__ recv) {
    int i = blockIdx.x * blockDim.x + threadIdx.x;
    if (i < N_EDGES) {
        int p = atomicAdd(&g_off[recv[i]], 1);
        g_idx[p] = i;
    }
}
__global__ void k_sortlists() {
    int n = blockIdx.x * blockDim.x + threadIdx.x;
    if (n >= N_NODES) return;
    int b = g_ptr[n], e2 = g_ptr[n + 1];
    for (int i = b + 1; i < e2; i++) {
        int v = g_idx[i];
        int j = i - 1;
        while (j >= b && g_idx[j] > v) {
            g_idx[j + 1] = g_idx[j];
            j--;
        }
        g_idx[j + 1] = v;
    }
}

// ---------------- embeddings ---------------------------------------------------
__global__ void __launch_bounds__(128, 2) k_node_emb(const float* __restrict__ nodes,
                                                     const float* __restrict__ w,
                                                     const float* __restrict__ b) {
    extern __shared__ float sm[];
    float* Xs = sm;
    float* Ws = sm + TM * XS_STRIDE;
    int tid = threadIdx.x, ty = tid >> 4, tx = tid & 15;
    int row0 = blockIdx.x * TM;
    u64 acc2[8][4];
    zero_acc2(acc2);
    for (int s = 0; s < 3; s++) {
        __syncthreads();
        for (int idx = tid; idx < TM * 48; idx += 128) {
            int r = idx / 48, c = idx % 48;
            int row = row0 + r;
            float2 v = make_float2(0.f, 0.f);
            if (row < N_NODES)
                v = __ldg(((const float2*)(nodes + (size_t)row * KEMB + s * 96)) + c);
            *(float2*)(Xs + r * XS_STRIDE + 2 * c) = v;
        }
        stage_W(Ws, w + s * 96 * D, 96 * 32, tid);
        __syncthreads();
        gemm128_p2(Xs, Ws, acc2, 96, ty, tx);
    }
    float acc[8][8];
    unpack_acc(acc2, acc);
    float bv[8];
#pragma unroll
    for (int j = 0; j < 8; j++) bv[j] = __ldg(b + tx * 8 + j);
#pragma unroll
    for (int i = 0; i < 8; i++)
#pragma unroll
        for (int j = 0; j < 8; j++) acc[i][j] += bv[j];
    plain_store(g_h, acc, row0, N_NODES, ty, tx);
}

__global__ void k_edge_emb(const float* __restrict__ edges,
                           const float* __restrict__ w, const float* __restrict__ b) {
    int idx = blockIdx.x * blockDim.x + threadIdx.x;
    if (idx >= N_EDGES * 32) return;
    int ei = idx >> 5, c4 = idx & 31;
    float e0 = __ldg(edges + ei * 2);
    float e1 = __ldg(edges + ei * 2 + 1);
    float4 w0 = __ldg(((const float4*)w) + c4);
    float4 w1 = __ldg(((const float4*)(w + D)) + c4);
    float4 bb = __ldg(((const float4*)b) + c4);
    float4 r;
    r.x = e0 * w0.x + e1 * w1.x + bb.x;
    r.y = e0 * w0.y + e1 * w1.y + bb.y;
    r.z = e0 * w0.z + e1 * w1.z + bb.z;
    r.w = e0 * w0.w + e1 * w1.w + bb.w;
    ((float4*)(g_e + (size_t)ei * D))[c4] = r;
}

// ---------------- scatter-mean aggregation (pull via CSR) ----------------------
__global__ void __launch_bounds__(256) k_agg() {
    int warp = (blockIdx.x * 256 + threadIdx.x) >> 5;
    int lane = threadIdx.x & 31;
    if (warp >= N_NODES) return;
    int b = g_ptr[warp], e2 = g_ptr[warp + 1];
    float4 a = make_float4(0.f, 0.f, 0.f, 0.f);
    for (int p = b; p < e2; p++) {
        int ei = g_idx[p];
        float4 v = *(const float4*)(g_e + (size_t)ei * D + lane * 4);
        a.x += v.x; a.y += v.y; a.z += v.z; a.w += v.w;
    }
    float ic = g_inv_cnt[warp];
    *(float4*)(g_agg + (size_t)warp * D + lane * 4) =
        make_float4(a.x * ic, a.y * ic, a.z * ic, a.w * ic);
}

// ---------------- output head --------------------------------------------------
__global__ void __launch_bounds__(128, 2) k_out(
    const float* __restrict__ w1, const float* __restrict__ b1,
    const float* __restrict__ lg, const float* __restrict__ lb,
    const float* __restrict__ pw, const float* __restrict__ pb,
    float* __restrict__ out) {
    extern __shared__ float sm[];
    float* Xs = sm;
    float* Ws = sm + TM * XS_STRIDE;
    int tid = threadIdx.x, ty = tid >> 4, tx = tid & 15;
    int row0 = blockIdx.x * TM;
    u64 acc2[8][4];
    zero_acc2(acc2);
    stage_X_rows(Xs, g_h, row0, N_NODES, tid);
    stage_W(Ws, w1, 128 * 32, tid);
    __syncthreads();
    gemm128_p2(Xs, Ws, acc2, 128, ty, tx);
    float acc[8][8];
    unpack_acc(acc2, acc);
    mlp_epilogue(acc, b1, lg, lb, tx);
    __syncthreads();
    acc_to_X(Xs, acc, ty, tx);
    stage_W(Ws, pw, (D * PRED) / 4, tid);
    __syncthreads();
    for (int idx = tid; idx < TM * PRED; idx += 128) {
        int r = idx / PRED, p = idx % PRED;
        int row = row0 + r;
        if (row < N_NODES) {
            float s = __ldg(pb + p);
            const float* xr = Xs + r * XS_STRIDE;
#pragma unroll 4
            for (int k = 0; k < D; k++) s += xr[k] * Ws[k * PRED + p];
            out[(size_t)row * PRED + p] = s;
        }
    }
}

// ---------------- launch -------------------------------------------------------
extern "C" void kernel_launch(void* const* d_in, const int* in_sizes, int n_in,
                              void* d_out, int out_size) {
    const float* nodes = (const float*)d_in[0];
    const float* edges = (const float*)d_in[1];
    const int* senders = (const int*)d_in[2];
    const int* receivers = (const int*)d_in[3];
    const float* w_ne = (const float*)d_in[4];
    const float* b_ne = (const float*)d_in[5];
    const float* w_ee = (const float*)d_in[6];
    const float* b_ee = (const float*)d_in[7];
    const float* epw = (const float*)d_in[8];
    const float* epb = (const float*)d_in[9];
    const float* npw = (const float*)d_in[10];
    const float* npb = (const float*)d_in[11];
    const float* emw = (const float*)d_in[12];
    const float* emb_ = (const float*)d_in[13];
    const float* elg = (const float*)d_in[14];
    const float* elb = (const float*)d_in[15];
    const float* nmw = (const float*)d_in[16];
    const float* nmb = (const float*)d_in[17];
    const float* nlg = (const float*)d_in[18];
    const float* nlb = (const float*)d_in[19];
    const float* ow = (const float*)d_in[20];
    const float* ob = (const float*)d_in[21];
    const float* og = (const float*)d_in[22];
    const float* obeta = (const float*)d_in[23];
    const float* pw = (const float*)d_in[24];
    const float* pb = (const float*)d_in[25];
    float* out = (float*)d_out;

    cudaFuncSetAttribute(k_edge_t, cudaFuncAttributeMaxDynamicSharedMemorySize, TS_BYTES);
    cudaFuncSetAttribute(k_node_t, cudaFuncAttributeMaxDynamicSharedMemorySize, TS_BYTES);
    cudaFuncSetAttribute(k_node_emb, cudaFuncAttributeMaxDynamicSharedMemorySize, SMEM_BYTES);
    cudaFuncSetAttribute(k_out, cudaFuncAttributeMaxDynamicSharedMemorySize, SMEM_BYTES);

    // CSR build (deterministic: per-node lists sorted by edge id)
    k_zero_deg<<<(N_NODES + 255) / 256, 256>>>();
    k_hist<<<(N_EDGES + 255) / 256, 256>>>(receivers);
    k_scan<<<1, 1024>>>();
    k_scatter<<<(N_EDGES + 255) / 256, 256>>>(receivers);
    k_sortlists<<<(N_NODES + 255) / 256, 256>>>();

    // embeddings
    k_node_emb<<<(N_NODES + TM - 1) / TM, 128, SMEM_BYTES>>>(nodes, w_ne, b_ne);
    k_edge_emb<<<(N_EDGES * 32 + 255) / 256, 256>>>(edges, w_ee, b_ee);

    // GNN layers (HMMA fused)
    for (int l = 0; l < 2; l++) {
        k_edge_t<<<N_EDGES / 128, 256, TS_BYTES>>>(
            senders, receivers, epw + l * 3 * D * D, epb + l * D,
            emw + l * 2 * D * D, emb_ + l * 2 * D, elg + l * 2 * D, elb + l * 2 * D);
        k_agg<<<(N_NODES * 32 + 255) / 256, 256>>>();
        k_node_t<<<(N_NODES + 127) / 128, 256, TS_BYTES>>>(
            npw + l * 2 * D * D, npb + l * D,
            nmw + l * 2 * D * D, nmb + l * 2 * D, nlg + l * 2 * D, nlb + l * 2 * D);
    }

    // output head
    k_out<<<(N_NODES + TM - 1) / TM, 128, SMEM_BYTES>>>(ow, ob, og, obeta, pw, pb, out);
}

// round 12
// speedup vs baseline: 1.6506x; 1.4111x over previous
#include <cuda_runtime.h>
#include <cuda_bf16.h>
#include <math.h>
#include <stdint.h>

#define N_NODES 20000
#define N_EDGES 320000
#define D 128
#define KEMB 288
#define PRED 24
#define EPSV 1e-5f

typedef unsigned long long u64;

// ---------------- scratch (device globals; no runtime alloc allowed) ----------
__device__ float g_h[N_NODES * D];
__device__ float g_e[N_EDGES * D];
__device__ float g_agg[N_NODES * D];
__device__ float g_inv_cnt[N_NODES];
__device__ int   g_deg[N_NODES];
__device__ int   g_ptr[N_NODES + 1];
__device__ int   g_off[N_NODES];
__device__ int   g_idx[N_EDGES];

// bf16 hi/lo mirrors (precomputed; 16B-aligned for uint4 access)
__device__ __align__(16) __nv_bfloat16 g_h16h[N_NODES * D];
__device__ __align__(16) __nv_bfloat16 g_h16l[N_NODES * D];
__device__ __align__(16) __nv_bfloat16 g_e16h[N_EDGES * D];
__device__ __align__(16) __nv_bfloat16 g_e16l[N_EDGES * D];
__device__ __align__(16) __nv_bfloat16 g_a16h[N_NODES * D];
__device__ __align__(16) __nv_bfloat16 g_a16l[N_NODES * D];
// 18 transposed weight matrices [c][k], tight 128x128 bf16 each
__device__ __align__(16) __nv_bfloat16 g_wth[18 * D * D];
__device__ __align__(16) __nv_bfloat16 g_wtl[18 * D * D];

// =====================================================================
// common helpers
// =====================================================================
__device__ __forceinline__ uint32_t smem_to_u32(const void* smem_ptr) {
    uint32_t addr;
    asm("{ .reg .u64 tmp; cvta.to.shared.u64 tmp, %1; cvt.u32.u64 %0, tmp; }"
        : "=r"(addr) : "l"(smem_ptr));
    return addr;
}

__device__ __forceinline__ uint32_t pack_bf16(float lo, float hi) {
    uint32_t r;
    asm("cvt.rn.bf16x2.f32 %0, %1, %2;" : "=r"(r) : "f"(hi), "f"(lo));
    return r;
}
__device__ __forceinline__ void split_pair(float a, float b, uint32_t& hi, uint32_t& lo) {
    float ah = __bfloat162float(__float2bfloat16(a));
    float bh = __bfloat162float(__float2bfloat16(b));
    hi = pack_bf16(a, b);
    lo = pack_bf16(a - ah, b - bh);
}

__device__ __forceinline__ float gelu_f(float x) {
    float u = 0.7978845608028654f * (x + 0.044715f * x * x * x);
    u = fminf(40.f, fmaxf(-40.f, u));
    float t = __expf(2.f * u);
    float th = __fdividef(t - 1.f, t + 1.f);
    return 0.5f * x * (1.f + th);
}

// =====================================================================
// tensor-core path (R5 geometry): 128-row tiles, 256 threads, 8 warps
// =====================================================================
#define AST 136                        // bf16 row stride (272B) -> conflict-free ldmatrix
#define TILE_BYTES (128 * AST * 2)     // 34816
#define TS_AHI 0
#define TS_ALO (TILE_BYTES)
#define TS_BHI (2 * TILE_BYTES)
#define TS_BLO (3 * TILE_BYTES)
#define TS_BYTES (4 * TILE_BYTES)      // 139264

__device__ __forceinline__ void ldsm4(uint32_t r[4], uint32_t addr) {
    asm volatile("ldmatrix.sync.aligned.m8n8.x4.shared.b16 {%0,%1,%2,%3}, [%4];"
                 : "=r"(r[0]), "=r"(r[1]), "=r"(r[2]), "=r"(r[3]) : "r"(addr));
}
__device__ __forceinline__ void mma_bf16(float d[4], const uint32_t a[4],
                                         uint32_t b0, uint32_t b1) {
    asm volatile(
        "mma.sync.aligned.m16n8k16.row.col.f32.bf16.bf16.f32 "
        "{%0,%1,%2,%3}, {%4,%5,%6,%7}, {%8,%9}, {%0,%1,%2,%3};"
        : "+f"(d[0]), "+f"(d[1]), "+f"(d[2]), "+f"(d[3])
        : "r"(a[0]), "r"(a[1]), "r"(a[2]), "r"(a[3]), "r"(b0), "r"(b1));
}
__device__ __forceinline__ uint32_t addrA(uint32_t base, int m0, int k0, int lane) {
    int r = m0 + (lane & 15);
    int c = k0 + ((lane >> 4) << 3);
    return base + (uint32_t)(r * AST + c) * 2;
}
__device__ __forceinline__ uint32_t addrB(uint32_t base, int n0, int k0, int lane) {
    int r = n0 + (lane & 7) + ((lane & 16) ? 8 : 0);
    int c = k0 + ((lane & 8) ? 8 : 0);
    return base + (uint32_t)(r * AST + c) * 2;
}

// stage A tile [128 rows x 128 bf16] hi+lo from mirrors via pure uint4 copies
__device__ __forceinline__ void stage_A16(char* smem,
                                          const __nv_bfloat16* __restrict__ hi,
                                          const __nv_bfloat16* __restrict__ lo,
                                          const int* __restrict__ gidx,
                                          int row0, int Mlim, int tid) {
    for (int it = tid; it < 128 * 16; it += 256) {
        int r = it >> 4, ch = it & 15;
        int row = row0 + r;
        uint4 vh = make_uint4(0u, 0u, 0u, 0u);
        uint4 vl = vh;
        if (row < Mlim) {
            size_t srow = gidx ? (size_t)__ldg(gidx + row) : (size_t)row;
            vh = __ldg((const uint4*)((const char*)(hi + srow * D) + ch * 16));
            vl = __ldg((const uint4*)((const char*)(lo + srow * D) + ch * 16));
        }
        uint32_t off = (uint32_t)(r * AST) * 2 + ch * 16;
        *(uint4*)(smem + TS_AHI + off) = vh;
        *(uint4*)(smem + TS_ALO + off) = vl;
    }
}

// stage B tile [128 x 128 bf16] hi+lo from transposed-weight mirrors (matrix widx)
__device__ __forceinline__ void stage_B16(char* smem, int widx, int tid) {
    const char* bh = (const char*)(g_wth + (size_t)widx * D * D);
    const char* bl = (const char*)(g_wtl + (size_t)widx * D * D);
    for (int it = tid; it < 128 * 16; it += 256) {
        int r = it >> 4, ch = it & 15;
        uint32_t off = (uint32_t)(r * AST) * 2 + ch * 16;
        *(uint4*)(smem + TS_BHI + off) = __ldg((const uint4*)(bh + r * 256 + ch * 16));
        *(uint4*)(smem + TS_BLO + off) = __ldg((const uint4*)(bl + r * 256 + ch * 16));
    }
}

// acc += X[warp rows 16 x 128] @ W^T[128 x 128], 3-product bf16 split
__device__ __forceinline__ void gemm_mma(uint32_t sb, float acc[16][4], int warp, int lane) {
    int m0 = warp * 16;
    uint32_t ahi = sb + TS_AHI, alo = sb + TS_ALO;
    uint32_t bhi = sb + TS_BHI, blo = sb + TS_BLO;
#pragma unroll
    for (int ks = 0; ks < 8; ks++) {
        int k0 = ks * 16;
        uint32_t ah[4], al[4];
        ldsm4(ah, addrA(ahi, m0, k0, lane));
        ldsm4(al, addrA(alo, m0, k0, lane));
#pragma unroll
        for (int nb = 0; nb < 8; nb++) {
            int n0 = nb * 16;
            uint32_t bh[4], bl[4];
            ldsm4(bh, addrB(bhi, n0, k0, lane));
            ldsm4(bl, addrB(blo, n0, k0, lane));
            mma_bf16(acc[2 * nb],     ah, bh[0], bh[1]);
            mma_bf16(acc[2 * nb],     ah, bl[0], bl[1]);
            mma_bf16(acc[2 * nb],     al, bh[0], bh[1]);
            mma_bf16(acc[2 * nb + 1], ah, bh[2], bh[3]);
            mma_bf16(acc[2 * nb + 1], ah, bl[2], bl[3]);
            mma_bf16(acc[2 * nb + 1], al, bh[2], bh[3]);
        }
    }
}

__device__ __forceinline__ void zero_acc16(float acc[16][4]) {
#pragma unroll
    for (int i = 0; i < 16; i++)
#pragma unroll
        for (int j = 0; j < 4; j++) acc[i][j] = 0.f;
}

// proj epilogue: acc + bias -> A_hi/A_lo in smem
__device__ __forceinline__ void epi_proj_mma(float acc[16][4], const float* __restrict__ pb,
                                             char* Ahi, char* Alo, int warp, int lane) {
    int rb = warp * 16 + (lane >> 2);
    int cb = 2 * (lane & 3);
#pragma unroll
    for (int half = 0; half < 2; half++) {
        int row = rb + half * 8;
#pragma unroll
        for (int nt = 0; nt < 16; nt++) {
            int col = nt * 8 + cb;
            float x = acc[nt][half * 2]     + __ldg(pb + col);
            float y = acc[nt][half * 2 + 1] + __ldg(pb + col + 1);
            uint32_t hi, lo;
            split_pair(x, y, hi, lo);
            uint32_t off = (uint32_t)(row * AST + col) * 2;
            *(uint32_t*)(Ahi + off) = hi;
            *(uint32_t*)(Alo + off) = lo;
        }
    }
}

// MLP epilogue: y = LN(gelu(acc + bias)); toA -> smem A, else residual-add to global
__device__ __forceinline__ void epi_ln_mma(float acc[16][4], const float* __restrict__ bias,
                                           const float* __restrict__ lg,
                                           const float* __restrict__ lb,
                                           bool toA, char* Ahi, char* Alo,
                                           float* __restrict__ dst, int row0, int Mlim,
                                           int warp, int lane) {
    int rb = warp * 16 + (lane >> 2);
    int cb = 2 * (lane & 3);
#pragma unroll
    for (int half = 0; half < 2; half++) {
        int row = rb + half * 8;
        float s1 = 0.f, s2 = 0.f;
#pragma unroll
        for (int nt = 0; nt < 16; nt++) {
            int col = nt * 8 + cb;
            float z0 = gelu_f(acc[nt][half * 2]     + __ldg(bias + col));
            float z1 = gelu_f(acc[nt][half * 2 + 1] + __ldg(bias + col + 1));
            acc[nt][half * 2] = z0;
            acc[nt][half * 2 + 1] = z1;
            s1 += z0 + z1;
            s2 += z0 * z0 + z1 * z1;
        }
        s1 += __shfl_xor_sync(0xffffffffu, s1, 1);
        s2 += __shfl_xor_sync(0xffffffffu, s2, 1);
        s1 += __shfl_xor_sync(0xffffffffu, s1, 2);
        s2 += __shfl_xor_sync(0xffffffffu, s2, 2);
        float m = s1 * (1.f / D);
        float var = s2 * (1.f / D) - m * m;
        float rs = rsqrtf(var + EPSV);
#pragma unroll
        for (int nt = 0; nt < 16; nt++) {
            int col = nt * 8 + cb;
            float y0 = (acc[nt][half * 2]     - m) * rs * __ldg(lg + col)     + __ldg(lb + col);
            float y1 = (acc[nt][half * 2 + 1] - m) * rs * __ldg(lg + col + 1) + __ldg(lb + col + 1);
            if (toA) {
                uint32_t hi, lo;
                split_pair(y0, y1, hi, lo);
                uint32_t off = (uint32_t)(row * AST + col) * 2;
                *(uint32_t*)(Ahi + off) = hi;
                *(uint32_t*)(Alo + off) = lo;
            } else if (row0 + row < Mlim) {
                float2* p = (float2*)(dst + (size_t)(row0 + row) * D + col);
                float2 v = *p;
                v.x += y0;
                v.y += y1;
                *p = v;
            }
        }
    }
}

// fused 128-row tile: proj (nchunks x K=128) + 2x MLP(LN(gelu)) + residual
__device__ void fused_tile(char* smem, int row0, int Mlim,
                           const __nv_bfloat16* x0h, const __nv_bfloat16* x0l, const int* gi0,
                           const __nv_bfloat16* x1h, const __nv_bfloat16* x1l, const int* gi1,
                           const __nv_bfloat16* x2h, const __nv_bfloat16* x2l, const int* gi2,
                           int nchunks, int wproj0, int wmlp0,
                           const float* pb, const float* mb,
                           const float* lg, const float* lb,
                           float* resid_dst) {
    uint32_t sb = smem_to_u32(smem);
    int tid = threadIdx.x, lane = tid & 31, warp = tid >> 5;
    float acc[16][4];
    zero_acc16(acc);

    // --- projection: accumulate nchunks K=128 pieces ---
    for (int c = 0; c < nchunks; c++) {
        const __nv_bfloat16* xh = (c == 0) ? x0h : (c == 1) ? x1h : x2h;
        const __nv_bfloat16* xl = (c == 0) ? x0l : (c == 1) ? x1l : x2l;
        const int* gi = (c == 0) ? gi0 : (c == 1) ? gi1 : gi2;
        stage_A16(smem, xh, xl, gi, row0, Mlim, tid);
        stage_B16(smem, wproj0 + c, tid);
        __syncthreads();
        gemm_mma(sb, acc, warp, lane);
        __syncthreads();
    }
    epi_proj_mma(acc, pb, smem + TS_AHI, smem + TS_ALO, warp, lane);

    // --- 2x MLP: LN(gelu(X@W + b)); last adds residual & stores ---
    for (int m = 0; m < 2; m++) {
        stage_B16(smem, wmlp0 + m, tid);
        __syncthreads();
        zero_acc16(acc);
        gemm_mma(sb, acc, warp, lane);
        __syncthreads();
        if (m == 0)
            epi_ln_mma(acc, mb, lg, lb, true, smem + TS_AHI, smem + TS_ALO,
                       nullptr, 0, 0, warp, lane);
        else
            epi_ln_mma(acc, mb + D, lg + D, lb + D, false, nullptr, nullptr,
                       resid_dst, row0, Mlim, warp, lane);
    }
}

__global__ void __launch_bounds__(256, 1) k_edge_t(
    const int* __restrict__ senders, const int* __restrict__ receivers,
    int wproj0, int wmlp0,
    const float* __restrict__ pb, const float* __restrict__ mb,
    const float* __restrict__ lg, const float* __restrict__ lb) {
    extern __shared__ char smem[];
    fused_tile(smem, blockIdx.x * 128, N_EDGES,
               g_e16h, g_e16l, nullptr,
               g_h16h, g_h16l, senders,
               g_h16h, g_h16l, receivers, 3,
               wproj0, wmlp0, pb, mb, lg, lb, g_e);
}

__global__ void __launch_bounds__(256, 1) k_node_t(
    int wproj0, int wmlp0,
    const float* __restrict__ pb, const float* __restrict__ mb,
    const float* __restrict__ lg, const float* __restrict__ lb) {
    extern __shared__ char smem[];
    fused_tile(smem, blockIdx.x * 128, N_NODES,
               g_h16h, g_h16l, nullptr,
               g_a16h, g_a16l, nullptr,
               nullptr, nullptr, nullptr, 2,
               wproj0, wmlp0, pb, mb, lg, lb, g_h);
}

// ---------------- precompute kernels (device globals referenced IN DEVICE CODE) --
__device__ __forceinline__ void conv_body(const float* __restrict__ src,
                                          __nv_bfloat16* __restrict__ dh,
                                          __nv_bfloat16* __restrict__ dl, int n4) {
    int idx = blockIdx.x * blockDim.x + threadIdx.x;
    if (idx >= n4) return;
    float4 v = __ldg(((const float4*)src) + idx);
    uint32_t h0, l0, h1, l1;
    split_pair(v.x, v.y, h0, l0);
    split_pair(v.z, v.w, h1, l1);
    ((uint2*)dh)[idx] = make_uint2(h0, h1);
    ((uint2*)dl)[idx] = make_uint2(l0, l1);
}
__global__ void k_conv_e() { conv_body(g_e, g_e16h, g_e16l, N_EDGES * D / 4); }
__global__ void k_conv_h() { conv_body(g_h, g_h16h, g_h16l, N_NODES * D / 4); }
__global__ void k_conv_a() { conv_body(g_agg, g_a16h, g_a16l, N_NODES * D / 4); }

// transpose + split the 18 GNN weight matrices into g_wth/g_wtl
__global__ void k_wprep(const float* __restrict__ epw, const float* __restrict__ emw,
                        const float* __restrict__ npw, const float* __restrict__ nmw) {
    int m = blockIdx.x;
    const float* src;
    if (m < 6) src = epw + (size_t)m * D * D;
    else if (m < 10) src = emw + (size_t)(m - 6) * D * D;
    else if (m < 14) src = npw + (size_t)(m - 10) * D * D;
    else src = nmw + (size_t)(m - 14) * D * D;
    __nv_bfloat16* dh = g_wth + (size_t)m * D * D;
    __nv_bfloat16* dl = g_wtl + (size_t)m * D * D;
    for (int idx = threadIdx.x; idx < D * D; idx += blockDim.x) {
        int k = idx >> 7, c = idx & 127;
        float v = __ldg(src + idx);
        __nv_bfloat16 h = __float2bfloat16(v);
        dh[c * D + k] = h;
        dl[c * D + k] = __float2bfloat16(v - __bfloat162float(h));
    }
}

// =====================================================================
// scalar FFMA2 path (embeddings / output head)
// =====================================================================
#define TM 64
#define XS_STRIDE 132
#define SMEM_BYTES ((TM * XS_STRIDE + D * D) * 4)

__device__ __forceinline__ u64 pack_dup(float x) {
    u64 r;
    asm("mov.b64 %0, {%1, %1};" : "=l"(r) : "f"(x));
    return r;
}
__device__ __forceinline__ void fma2(u64& d, u64 a, u64 b) {
    asm("fma.rn.f32x2 %0, %1, %2, %0;" : "+l"(d) : "l"(a), "l"(b));
}
__device__ __forceinline__ void unpack2(u64 v, float& lo, float& hi) {
    asm("mov.b64 {%0, %1}, %2;" : "=f"(lo), "=f"(hi) : "l"(v));
}
__device__ __forceinline__ void zero_acc2(u64 a2[8][4]) {
#pragma unroll
    for (int i = 0; i < 8; i++)
#pragma unroll
        for (int p = 0; p < 4; p++) a2[i][p] = 0ULL;
}
__device__ __forceinline__ void unpack_acc(const u64 a2[8][4], float acc[8][8]) {
#pragma unroll
    for (int i = 0; i < 8; i++)
#pragma unroll
        for (int p = 0; p < 4; p++) unpack2(a2[i][p], acc[i][2 * p], acc[i][2 * p + 1]);
}
__device__ __forceinline__ void stage_W(float* Ws, const float* __restrict__ src, int n4, int tid) {
    for (int idx = tid; idx < n4; idx += 128)
        ((float4*)Ws)[idx] = __ldg(((const float4*)src) + idx);
}
__device__ __forceinline__ void stage_X_rows(float* Xs, const float* __restrict__ src,
                                             int row0, int M, int tid) {
    for (int idx = tid; idx < TM * 64; idx += 128) {
        int r = idx >> 6, c = idx & 63;
        int row = row0 + r;
        float2 v = make_float2(0.f, 0.f);
        if (row < M) v = __ldg(((const float2*)(src + (size_t)row * D)) + c);
        *(float2*)(Xs + r * XS_STRIDE + 2 * c) = v;
    }
}
__device__ __forceinline__ void gemm128_p2(const float* Xs, const float* Ws,
                                           u64 acc2[8][4], int K, int ty, int tx) {
    const float* xb = Xs + ty * 8 * XS_STRIDE;
    const float* wb = Ws + tx * 8;
#pragma unroll 2
    for (int k0 = 0; k0 < K; k0 += 4) {
        float4 av[8];
#pragma unroll
        for (int i = 0; i < 8; i++)
            av[i] = *(const float4*)(xb + i * XS_STRIDE + k0);
#pragma unroll
        for (int kk = 0; kk < 4; kk++) {
            const ulonglong2* w2 = (const ulonglong2*)(wb + (k0 + kk) * D);
            ulonglong2 b01 = w2[0];
            ulonglong2 b23 = w2[1];
#pragma unroll
            for (int i = 0; i < 8; i++) {
                float a = (kk == 0) ? av[i].x : (kk == 1) ? av[i].y
                        : (kk == 2) ? av[i].z : av[i].w;
                u64 ap = pack_dup(a);
                fma2(acc2[i][0], ap, b01.x);
                fma2(acc2[i][1], ap, b01.y);
                fma2(acc2[i][2], ap, b23.x);
                fma2(acc2[i][3], ap, b23.y);
            }
        }
    }
}
__device__ __forceinline__ void acc_to_X(float* Xs, const float acc[8][8], int ty, int tx) {
#pragma unroll
    for (int i = 0; i < 8; i++)
#pragma unroll
        for (int jp = 0; jp < 4; jp++)
            *(float2*)(Xs + (ty * 8 + i) * XS_STRIDE + tx * 8 + 2 * jp) =
                make_float2(acc[i][2 * jp], acc[i][2 * jp + 1]);
}
__device__ __forceinline__ void mlp_epilogue(float acc[8][8],
                                             const float* __restrict__ bias,
                                             const float* __restrict__ lg,
                                             const float* __restrict__ lb, int tx) {
    float bv[8], gv[8], bev[8];
#pragma unroll
    for (int j = 0; j < 8; j++) {
        bv[j] = __ldg(bias + tx * 8 + j);
        gv[j] = __ldg(lg + tx * 8 + j);
        bev[j] = __ldg(lb + tx * 8 + j);
    }
#pragma unroll
    for (int i = 0; i < 8; i++) {
        float s1 = 0.f, s2 = 0.f;
#pragma unroll
        for (int j = 0; j < 8; j++) {
            float z = gelu_f(acc[i][j] + bv[j]);
            acc[i][j] = z;
            s1 += z;
            s2 += z * z;
        }
#pragma unroll
        for (int o = 8; o >= 1; o >>= 1) {
            s1 += __shfl_xor_sync(0xffffffffu, s1, o);
            s2 += __shfl_xor_sync(0xffffffffu, s2, o);
        }
        float m = s1 * (1.f / D);
        float var = s2 * (1.f / D) - m * m;
        float rs = rsqrtf(var + EPSV);
#pragma unroll
        for (int j = 0; j < 8; j++)
            acc[i][j] = (acc[i][j] - m) * rs * gv[j] + bev[j];
    }
}
__device__ __forceinline__ void plain_store(float* dst, const float acc[8][8],
                                            int row0, int M, int ty, int tx) {
#pragma unroll
    for (int i = 0; i < 8; i++) {
        int row = row0 + ty * 8 + i;
        if (row < M) {
            float2* p = (float2*)(dst + (size_t)row * D + tx * 8);
#pragma unroll
            for (int jp = 0; jp < 4; jp++)
                p[jp] = make_float2(acc[i][2 * jp], acc[i][2 * jp + 1]);
        }
    }
}

// ---------------- CSR construction --------------------------------------------
__global__ void k_zero_deg() {
    int i = blockIdx.x * blockDim.x + threadIdx.x;
    if (i < N_NODES) g_deg[i] = 0;
}
__global__ void k_hist(const int* __restrict__ recv) {
    int i = blockIdx.x * blockDim.x + threadIdx.x;
    if (i < N_EDGES) atomicAdd(&g_deg[recv[i]], 1);
}
__global__ void k_scan() {
    __shared__ int partial[1024];
    const int CH = (N_NODES + 1023) / 1024;
    int t = threadIdx.x;
    int start = t * CH;
    int end = min(start + CH, N_NODES);
    int s = 0;
    for (int i = start; i < end; i++) s += g_deg[i];
    partial[t] = s;
    __syncthreads();
    for (int o = 1; o < 1024; o <<= 1) {
        int v = (t >= o) ? partial[t - o] : 0;
        __syncthreads();
        partial[t] += v;
        __syncthreads();
    }
    int run = partial[t] - s;
    for (int i = start; i < end; i++) {
        int d = g_deg[i];
        g_ptr[i] = run;
        g_off[i] = run;
        g_inv_cnt[i] = 1.0f / (float)max(d, 1);
        run += d;
    }
    if (t == 0) g_ptr[N_NODES] = N_EDGES;
}
__global__ void k_scatter(const int* __restrict__ recv) {
    int i = blockIdx.x * blockDim.x + threadIdx.x;
    if (i < N_EDGES) {
        int p = atomicAdd(&g_off[recv[i]], 1);
        g_idx[p] = i;
    }
}
__global__ void k_sortlists() {
    int n = blockIdx.x * blockDim.x + threadIdx.x;
    if (n >= N_NODES) return;
    int b = g_ptr[n], e2 = g_ptr[n + 1];
    for (int i = b + 1; i < e2; i++) {
        int v = g_idx[i];
        int j = i - 1;
        while (j >= b && g_idx[j] > v) {
            g_idx[j + 1] = g_idx[j];
            j--;
        }
        g_idx[j + 1] = v;
    }
}

// ---------------- embeddings ---------------------------------------------------
__global__ void __launch_bounds__(128, 2) k_node_emb(const float* __restrict__ nodes,
                                                     const float* __restrict__ w,
                                                     const float* __restrict__ b) {
    extern __shared__ float sm[];
    float* Xs = sm;
    float* Ws = sm + TM * XS_STRIDE;
    int tid = threadIdx.x, ty = tid >> 4, tx = tid & 15;
    int row0 = blockIdx.x * TM;
    u64 acc2[8][4];
    zero_acc2(acc2);
    for (int s = 0; s < 3; s++) {
        __syncthreads();
        for (int idx = tid; idx < TM * 48; idx += 128) {
            int r = idx / 48, c = idx % 48;
            int row = row0 + r;
            float2 v = make_float2(0.f, 0.f);
            if (row < N_NODES)
                v = __ldg(((const float2*)(nodes + (size_t)row * KEMB + s * 96)) + c);
            *(float2*)(Xs + r * XS_STRIDE + 2 * c) = v;
        }
        stage_W(Ws, w + s * 96 * D, 96 * 32, tid);
        __syncthreads();
        gemm128_p2(Xs, Ws, acc2, 96, ty, tx);
    }
    float acc[8][8];
    unpack_acc(acc2, acc);
    float bv[8];
#pragma unroll
    for (int j = 0; j < 8; j++) bv[j] = __ldg(b + tx * 8 + j);
#pragma unroll
    for (int i = 0; i < 8; i++)
#pragma unroll
        for (int j = 0; j < 8; j++) acc[i][j] += bv[j];
    plain_store(g_h, acc, row0, N_NODES, ty, tx);
}

__global__ void k_edge_emb(const float* __restrict__ edges,
                           const float* __restrict__ w, const float* __restrict__ b) {
    int idx = blockIdx.x * blockDim.x + threadIdx.x;
    if (idx >= N_EDGES * 32) return;
    int ei = idx >> 5, c4 = idx & 31;
    float e0 = __ldg(edges + ei * 2);
    float e1 = __ldg(edges + ei * 2 + 1);
    float4 w0 = __ldg(((const float4*)w) + c4);
    float4 w1 = __ldg(((const float4*)(w + D)) + c4);
    float4 bb = __ldg(((const float4*)b) + c4);
    float4 r;
    r.x = e0 * w0.x + e1 * w1.x + bb.x;
    r.y = e0 * w0.y + e1 * w1.y + bb.y;
    r.z = e0 * w0.z + e1 * w1.z + bb.z;
    r.w = e0 * w0.w + e1 * w1.w + bb.w;
    ((float4*)(g_e + (size_t)ei * D))[c4] = r;
}

// ---------------- scatter-mean aggregation (pull via CSR) ----------------------
__global__ void __launch_bounds__(256) k_agg() {
    int warp = (blockIdx.x * 256 + threadIdx.x) >> 5;
    int lane = threadIdx.x & 31;
    if (warp >= N_NODES) return;
    int b = g_ptr[warp], e2 = g_ptr[warp + 1];
    float4 a = make_float4(0.f, 0.f, 0.f, 0.f);
    for (int p = b; p < e2; p++) {
        int ei = g_idx[p];
        float4 v = *(const float4*)(g_e + (size_t)ei * D + lane * 4);
        a.x += v.x; a.y += v.y; a.z += v.z; a.w += v.w;
    }
    float ic = g_inv_cnt[warp];
    *(float4*)(g_agg + (size_t)warp * D + lane * 4) =
        make_float4(a.x * ic, a.y * ic, a.z * ic, a.w * ic);
}

// ---------------- output head --------------------------------------------------
__global__ void __launch_bounds__(128, 2) k_out(
    const float* __restrict__ w1, const float* __restrict__ b1,
    const float* __restrict__ lg, const float* __restrict__ lb,
    const float* __restrict__ pw, const float* __restrict__ pb,
    float* __restrict__ out) {
    extern __shared__ float sm[];
    float* Xs = sm;
    float* Ws = sm + TM * XS_STRIDE;
    int tid = threadIdx.x, ty = tid >> 4, tx = tid & 15;
    int row0 = blockIdx.x * TM;
    u64 acc2[8][4];
    zero_acc2(acc2);
    stage_X_rows(Xs, g_h, row0, N_NODES, tid);
    stage_W(Ws, w1, 128 * 32, tid);
    __syncthreads();
    gemm128_p2(Xs, Ws, acc2, 128, ty, tx);
    float acc[8][8];
    unpack_acc(acc2, acc);
    mlp_epilogue(acc, b1, lg, lb, tx);
    __syncthreads();
    acc_to_X(Xs, acc, ty, tx);
    stage_W(Ws, pw, (D * PRED) / 4, tid);
    __syncthreads();
    for (int idx = tid; idx < TM * PRED; idx += 128) {
        int r = idx / PRED, p = idx % PRED;
        int row = row0 + r;
        if (row < N_NODES) {
            float s = __ldg(pb + p);
            const float* xr = Xs + r * XS_STRIDE;
#pragma unroll 4
            for (int k = 0; k < D; k++) s += xr[k] * Ws[k * PRED + p];
            out[(size_t)row * PRED + p] = s;
        }
    }
}

// ---------------- launch -------------------------------------------------------
extern "C" void kernel_launch(void* const* d_in, const int* in_sizes, int n_in,
                              void* d_out, int out_size) {
    const float* nodes = (const float*)d_in[0];
    const float* edges = (const float*)d_in[1];
    const int* senders = (const int*)d_in[2];
    const int* receivers = (const int*)d_in[3];
    const float* w_ne = (const float*)d_in[4];
    const float* b_ne = (const float*)d_in[5];
    const float* w_ee = (const float*)d_in[6];
    const float* b_ee = (const float*)d_in[7];
    const float* epw = (const float*)d_in[8];
    const float* epb = (const float*)d_in[9];
    const float* npw = (const float*)d_in[10];
    const float* npb = (const float*)d_in[11];
    const float* emw = (const float*)d_in[12];
    const float* emb_ = (const float*)d_in[13];
    const float* elg = (const float*)d_in[14];
    const float* elb = (const float*)d_in[15];
    const float* nmw = (const float*)d_in[16];
    const float* nmb = (const float*)d_in[17];
    const float* nlg = (const float*)d_in[18];
    const float* nlb = (const float*)d_in[19];
    const float* ow = (const float*)d_in[20];
    const float* ob = (const float*)d_in[21];
    const float* og = (const float*)d_in[22];
    const float* obeta = (const float*)d_in[23];
    const float* pw = (const float*)d_in[24];
    const float* pb = (const float*)d_in[25];
    float* out = (float*)d_out;

    cudaFuncSetAttribute(k_edge_t, cudaFuncAttributeMaxDynamicSharedMemorySize, TS_BYTES);
    cudaFuncSetAttribute(k_node_t, cudaFuncAttributeMaxDynamicSharedMemorySize, TS_BYTES);
    cudaFuncSetAttribute(k_node_emb, cudaFuncAttributeMaxDynamicSharedMemorySize, SMEM_BYTES);
    cudaFuncSetAttribute(k_out, cudaFuncAttributeMaxDynamicSharedMemorySize, SMEM_BYTES);

    // weight prep (transpose + bf16 hi/lo split of all 18 GNN matrices)
    k_wprep<<<18, 256>>>(epw, emw, npw, nmw);

    // CSR build (deterministic: per-node lists sorted by edge id)
    k_zero_deg<<<(N_NODES + 255) / 256, 256>>>();
    k_hist<<<(N_EDGES + 255) / 256, 256>>>(receivers);
    k_scan<<<1, 1024>>>();
    k_scatter<<<(N_EDGES + 255) / 256, 256>>>(receivers);
    k_sortlists<<<(N_NODES + 255) / 256, 256>>>();

    // embeddings
    k_node_emb<<<(N_NODES + TM - 1) / TM, 128, SMEM_BYTES>>>(nodes, w_ne, b_ne);
    k_edge_emb<<<(N_EDGES * 32 + 255) / 256, 256>>>(edges, w_ee, b_ee);

    const int n4_e = N_EDGES * D / 4;
    const int n4_n = N_NODES * D / 4;

    // GNN layers (HMMA fused, pure-copy staging of precomputed bf16 mirrors)
    for (int l = 0; l < 2; l++) {
        k_conv_e<<<(n4_e + 255) / 256, 256>>>();
        k_conv_h<<<(n4_n + 255) / 256, 256>>>();
        k_edge_t<<<N_EDGES / 128, 256, TS_BYTES>>>(
            senders, receivers, l * 3, 6 + 2 * l,
            epb + l * D, emb_ + l * 2 * D, elg + l * 2 * D, elb + l * 2 * D);
        k_agg<<<(N_NODES * 32 + 255) / 256, 256>>>();
        k_conv_a<<<(n4_n + 255) / 256, 256>>>();
        k_node_t<<<(N_NODES + 127) / 128, 256, TS_BYTES>>>(
            10 + 2 * l, 14 + 2 * l,
            npb + l * D, nmb + l * 2 * D, nlg + l * 2 * D, nlb + l * 2 * D);
    }

    // output head
    k_out<<<(N_NODES + TM - 1) / TM, 128, SMEM_BYTES>>>(ow, ob, og, obeta, pw, pb, out);
}

// round 13
// speedup vs baseline: 1.7468x; 1.0583x over previous
#include <cuda_runtime.h>
#include <cuda_bf16.h>
#include <math.h>
#include <stdint.h>

#define N_NODES 20000
#define N_EDGES 320000
#define D 128
#define KEMB 288
#define PRED 24
#define EPSV 1e-5f

typedef unsigned long long u64;

// ---------------- scratch (device globals; no runtime alloc allowed) ----------
__device__ float g_h[N_NODES * D];
__device__ float g_e[N_EDGES * D];
__device__ float g_agg[N_NODES * D];
__device__ float g_inv_cnt[N_NODES];
__device__ int   g_deg[N_NODES];
__device__ int   g_ptr[N_NODES + 1];
__device__ int   g_off[N_NODES];
__device__ int   g_idx[N_EDGES];

// bf16 hi/lo mirrors (precomputed; 16B-aligned for uint4 access)
__device__ __align__(16) __nv_bfloat16 g_h16h[N_NODES * D];
__device__ __align__(16) __nv_bfloat16 g_h16l[N_NODES * D];
__device__ __align__(16) __nv_bfloat16 g_e16h[N_EDGES * D];
__device__ __align__(16) __nv_bfloat16 g_e16l[N_EDGES * D];
__device__ __align__(16) __nv_bfloat16 g_a16h[N_NODES * D];
__device__ __align__(16) __nv_bfloat16 g_a16l[N_NODES * D];
// 18 transposed weight matrices [c][k], tight 128x128 bf16 each
__device__ __align__(16) __nv_bfloat16 g_wth[18 * D * D];
__device__ __align__(16) __nv_bfloat16 g_wtl[18 * D * D];

// =====================================================================
// common helpers
// =====================================================================
__device__ __forceinline__ uint32_t smem_to_u32(const void* smem_ptr) {
    uint32_t addr;
    asm("{ .reg .u64 tmp; cvta.to.shared.u64 tmp, %1; cvt.u32.u64 %0, tmp; }"
        : "=r"(addr) : "l"(smem_ptr));
    return addr;
}

__device__ __forceinline__ uint32_t pack_bf16(float lo, float hi) {
    uint32_t r;
    asm("cvt.rn.bf16x2.f32 %0, %1, %2;" : "=r"(r) : "f"(hi), "f"(lo));
    return r;
}
__device__ __forceinline__ void split_pair(float a, float b, uint32_t& hi, uint32_t& lo) {
    float ah = __bfloat162float(__float2bfloat16(a));
    float bh = __bfloat162float(__float2bfloat16(b));
    hi = pack_bf16(a, b);
    lo = pack_bf16(a - ah, b - bh);
}

__device__ __forceinline__ float gelu_f(float x) {
    float u = 0.7978845608028654f * (x + 0.044715f * x * x * x);
    u = fminf(40.f, fmaxf(-40.f, u));
    float t = __expf(2.f * u);
    float th = __fdividef(t - 1.f, t + 1.f);
    return 0.5f * x * (1.f + th);
}

// =====================================================================
// tensor-core path: 64-row tiles, 128 threads, 4 warps -> 2 CTAs/SM
// =====================================================================
#define AST 136                        // bf16 row stride (272B) -> conflict-free ldmatrix
#define TMROWS 64
#define NTHR 128
#define A_TILE (TMROWS * AST * 2)      // 17408
#define B_TILE (128 * AST * 2)         // 34816
#define TS_AHI 0
#define TS_ALO (A_TILE)                // 17408
#define TS_BHI (2 * A_TILE)            // 34816
#define TS_BLO (2 * A_TILE + B_TILE)   // 69632
#define TS_BYTES (2 * A_TILE + 2 * B_TILE)  // 104448 -> 2 CTAs/SM

__device__ __forceinline__ void ldsm4(uint32_t r[4], uint32_t addr) {
    asm volatile("ldmatrix.sync.aligned.m8n8.x4.shared.b16 {%0,%1,%2,%3}, [%4];"
                 : "=r"(r[0]), "=r"(r[1]), "=r"(r[2]), "=r"(r[3]) : "r"(addr));
}
__device__ __forceinline__ void mma_bf16(float d[4], const uint32_t a[4],
                                         uint32_t b0, uint32_t b1) {
    asm volatile(
        "mma.sync.aligned.m16n8k16.row.col.f32.bf16.bf16.f32 "
        "{%0,%1,%2,%3}, {%4,%5,%6,%7}, {%8,%9}, {%0,%1,%2,%3};"
        : "+f"(d[0]), "+f"(d[1]), "+f"(d[2]), "+f"(d[3])
        : "r"(a[0]), "r"(a[1]), "r"(a[2]), "r"(a[3]), "r"(b0), "r"(b1));
}
__device__ __forceinline__ uint32_t addrA(uint32_t base, int m0, int k0, int lane) {
    int r = m0 + (lane & 15);
    int c = k0 + ((lane >> 4) << 3);
    return base + (uint32_t)(r * AST + c) * 2;
}
__device__ __forceinline__ uint32_t addrB(uint32_t base, int n0, int k0, int lane) {
    int r = n0 + (lane & 7) + ((lane & 16) ? 8 : 0);
    int c = k0 + ((lane & 8) ? 8 : 0);
    return base + (uint32_t)(r * AST + c) * 2;
}

// stage A tile [64 rows x 128 bf16] hi+lo from mirrors via pure uint4 copies
__device__ __forceinline__ void stage_A16(char* smem,
                                          const __nv_bfloat16* __restrict__ hi,
                                          const __nv_bfloat16* __restrict__ lo,
                                          const int* __restrict__ gidx,
                                          int row0, int Mlim, int tid) {
    for (int it = tid; it < TMROWS * 16; it += NTHR) {
        int r = it >> 4, ch = it & 15;
        int row = row0 + r;
        uint4 vh = make_uint4(0u, 0u, 0u, 0u);
        uint4 vl = vh;
        if (row < Mlim) {
            size_t srow = gidx ? (size_t)__ldg(gidx + row) : (size_t)row;
            vh = __ldg((const uint4*)((const char*)(hi + srow * D) + ch * 16));
            vl = __ldg((const uint4*)((const char*)(lo + srow * D) + ch * 16));
        }
        uint32_t off = (uint32_t)(r * AST) * 2 + ch * 16;
        *(uint4*)(smem + TS_AHI + off) = vh;
        *(uint4*)(smem + TS_ALO + off) = vl;
    }
}

// stage B tile [128 x 128 bf16] hi+lo from transposed-weight mirrors (matrix widx)
__device__ __forceinline__ void stage_B16(char* smem, int widx, int tid) {
    const char* bh = (const char*)(g_wth + (size_t)widx * D * D);
    const char* bl = (const char*)(g_wtl + (size_t)widx * D * D);
    for (int it = tid; it < 128 * 16; it += NTHR) {
        int r = it >> 4, ch = it & 15;
        uint32_t off = (uint32_t)(r * AST) * 2 + ch * 16;
        *(uint4*)(smem + TS_BHI + off) = __ldg((const uint4*)(bh + r * 256 + ch * 16));
        *(uint4*)(smem + TS_BLO + off) = __ldg((const uint4*)(bl + r * 256 + ch * 16));
    }
}

// acc += X[warp rows 16 x 128] @ W^T[128 x 128], 3-product bf16 split
__device__ __forceinline__ void gemm_mma(uint32_t sb, float acc[16][4], int warp, int lane) {
    int m0 = warp * 16;
    uint32_t ahi = sb + TS_AHI, alo = sb + TS_ALO;
    uint32_t bhi = sb + TS_BHI, blo = sb + TS_BLO;
#pragma unroll
    for (int ks = 0; ks < 8; ks++) {
        int k0 = ks * 16;
        uint32_t ah[4], al[4];
        ldsm4(ah, addrA(ahi, m0, k0, lane));
        ldsm4(al, addrA(alo, m0, k0, lane));
#pragma unroll
        for (int nb = 0; nb < 8; nb++) {
            int n0 = nb * 16;
            uint32_t bh[4], bl[4];
            ldsm4(bh, addrB(bhi, n0, k0, lane));
            ldsm4(bl, addrB(blo, n0, k0, lane));
            mma_bf16(acc[2 * nb],     ah, bh[0], bh[1]);
            mma_bf16(acc[2 * nb],     ah, bl[0], bl[1]);
            mma_bf16(acc[2 * nb],     al, bh[0], bh[1]);
            mma_bf16(acc[2 * nb + 1], ah, bh[2], bh[3]);
            mma_bf16(acc[2 * nb + 1], ah, bl[2], bl[3]);
            mma_bf16(acc[2 * nb + 1], al, bh[2], bh[3]);
        }
    }
}

__device__ __forceinline__ void zero_acc16(float acc[16][4]) {
#pragma unroll
    for (int i = 0; i < 16; i++)
#pragma unroll
        for (int j = 0; j < 4; j++) acc[i][j] = 0.f;
}

// proj epilogue: acc + bias -> A_hi/A_lo in smem
__device__ __forceinline__ void epi_proj_mma(float acc[16][4], const float* __restrict__ pb,
                                             char* Ahi, char* Alo, int warp, int lane) {
    int rb = warp * 16 + (lane >> 2);
    int cb = 2 * (lane & 3);
#pragma unroll
    for (int half = 0; half < 2; half++) {
        int row = rb + half * 8;
#pragma unroll
        for (int nt = 0; nt < 16; nt++) {
            int col = nt * 8 + cb;
            float x = acc[nt][half * 2]     + __ldg(pb + col);
            float y = acc[nt][half * 2 + 1] + __ldg(pb + col + 1);
            uint32_t hi, lo;
            split_pair(x, y, hi, lo);
            uint32_t off = (uint32_t)(row * AST + col) * 2;
            *(uint32_t*)(Ahi + off) = hi;
            *(uint32_t*)(Alo + off) = lo;
        }
    }
}

// MLP epilogue: y = LN(gelu(acc + bias)); toA -> smem A, else residual-add to global
__device__ __forceinline__ void epi_ln_mma(float acc[16][4], const float* __restrict__ bias,
                                           const float* __restrict__ lg,
                                           const float* __restrict__ lb,
                                           bool toA, char* Ahi, char* Alo,
                                           float* __restrict__ dst, int row0, int Mlim,
                                           int warp, int lane) {
    int rb = warp * 16 + (lane >> 2);
    int cb = 2 * (lane & 3);
#pragma unroll
    for (int half = 0; half < 2; half++) {
        int row = rb + half * 8;
        float s1 = 0.f, s2 = 0.f;
#pragma unroll
        for (int nt = 0; nt < 16; nt++) {
            int col = nt * 8 + cb;
            float z0 = gelu_f(acc[nt][half * 2]     + __ldg(bias + col));
            float z1 = gelu_f(acc[nt][half * 2 + 1] + __ldg(bias + col + 1));
            acc[nt][half * 2] = z0;
            acc[nt][half * 2 + 1] = z1;
            s1 += z0 + z1;
            s2 += z0 * z0 + z1 * z1;
        }
        s1 += __shfl_xor_sync(0xffffffffu, s1, 1);
        s2 += __shfl_xor_sync(0xffffffffu, s2, 1);
        s1 += __shfl_xor_sync(0xffffffffu, s1, 2);
        s2 += __shfl_xor_sync(0xffffffffu, s2, 2);
        float m = s1 * (1.f / D);
        float var = s2 * (1.f / D) - m * m;
        float rs = rsqrtf(var + EPSV);
#pragma unroll
        for (int nt = 0; nt < 16; nt++) {
            int col = nt * 8 + cb;
            float y0 = (acc[nt][half * 2]     - m) * rs * __ldg(lg + col)     + __ldg(lb + col);
            float y1 = (acc[nt][half * 2 + 1] - m) * rs * __ldg(lg + col + 1) + __ldg(lb + col + 1);
            if (toA) {
                uint32_t hi, lo;
                split_pair(y0, y1, hi, lo);
                uint32_t off = (uint32_t)(row * AST + col) * 2;
                *(uint32_t*)(Ahi + off) = hi;
                *(uint32_t*)(Alo + off) = lo;
            } else if (row0 + row < Mlim) {
                float2* p = (float2*)(dst + (size_t)(row0 + row) * D + col);
                float2 v = *p;
                v.x += y0;
                v.y += y1;
                *p = v;
            }
        }
    }
}

// fused 64-row tile: proj (nchunks x K=128) + 2x MLP(LN(gelu)) + residual
__device__ void fused_tile(char* smem, int row0, int Mlim,
                           const __nv_bfloat16* x0h, const __nv_bfloat16* x0l, const int* gi0,
                           const __nv_bfloat16* x1h, const __nv_bfloat16* x1l, const int* gi1,
                           const __nv_bfloat16* x2h, const __nv_bfloat16* x2l, const int* gi2,
                           int nchunks, int wproj0, int wmlp0,
                           const float* pb, const float* mb,
                           const float* lg, const float* lb,
                           float* resid_dst) {
    uint32_t sb = smem_to_u32(smem);
    int tid = threadIdx.x, lane = tid & 31, warp = tid >> 5;
    float acc[16][4];
    zero_acc16(acc);

    // --- projection: accumulate nchunks K=128 pieces ---
    for (int c = 0; c < nchunks; c++) {
        const __nv_bfloat16* xh = (c == 0) ? x0h : (c == 1) ? x1h : x2h;
        const __nv_bfloat16* xl = (c == 0) ? x0l : (c == 1) ? x1l : x2l;
        const int* gi = (c == 0) ? gi0 : (c == 1) ? gi1 : gi2;
        stage_A16(smem, xh, xl, gi, row0, Mlim, tid);
        stage_B16(smem, wproj0 + c, tid);
        __syncthreads();
        gemm_mma(sb, acc, warp, lane);
        __syncthreads();
    }
    epi_proj_mma(acc, pb, smem + TS_AHI, smem + TS_ALO, warp, lane);

    // --- 2x MLP: LN(gelu(X@W + b)); last adds residual & stores ---
    for (int m = 0; m < 2; m++) {
        stage_B16(smem, wmlp0 + m, tid);
        __syncthreads();
        zero_acc16(acc);
        gemm_mma(sb, acc, warp, lane);
        __syncthreads();
        if (m == 0)
            epi_ln_mma(acc, mb, lg, lb, true, smem + TS_AHI, smem + TS_ALO,
                       nullptr, 0, 0, warp, lane);
        else
            epi_ln_mma(acc, mb + D, lg + D, lb + D, false, nullptr, nullptr,
                       resid_dst, row0, Mlim, warp, lane);
    }
}

__global__ void __launch_bounds__(NTHR, 2) k_edge_t(
    const int* __restrict__ senders, const int* __restrict__ receivers,
    int wproj0, int wmlp0,
    const float* __restrict__ pb, const float* __restrict__ mb,
    const float* __restrict__ lg, const float* __restrict__ lb) {
    extern __shared__ char smem[];
    fused_tile(smem, blockIdx.x * TMROWS, N_EDGES,
               g_e16h, g_e16l, nullptr,
               g_h16h, g_h16l, senders,
               g_h16h, g_h16l, receivers, 3,
               wproj0, wmlp0, pb, mb, lg, lb, g_e);
}

__global__ void __launch_bounds__(NTHR, 2) k_node_t(
    int wproj0, int wmlp0,
    const float* __restrict__ pb, const float* __restrict__ mb,
    const float* __restrict__ lg, const float* __restrict__ lb) {
    extern __shared__ char smem[];
    fused_tile(smem, blockIdx.x * TMROWS, N_NODES,
               g_h16h, g_h16l, nullptr,
               g_a16h, g_a16l, nullptr,
               nullptr, nullptr, nullptr, 2,
               wproj0, wmlp0, pb, mb, lg, lb, g_h);
}

// ---------------- precompute kernels (device globals referenced IN DEVICE CODE) --
__device__ __forceinline__ void conv_body(const float* __restrict__ src,
                                          __nv_bfloat16* __restrict__ dh,
                                          __nv_bfloat16* __restrict__ dl, int n4) {
    int idx = blockIdx.x * blockDim.x + threadIdx.x;
    if (idx >= n4) return;
    float4 v = __ldg(((const float4*)src) + idx);
    uint32_t h0, l0, h1, l1;
    split_pair(v.x, v.y, h0, l0);
    split_pair(v.z, v.w, h1, l1);
    ((uint2*)dh)[idx] = make_uint2(h0, h1);
    ((uint2*)dl)[idx] = make_uint2(l0, l1);
}
__global__ void k_conv_e() { conv_body(g_e, g_e16h, g_e16l, N_EDGES * D / 4); }
__global__ void k_conv_h() { conv_body(g_h, g_h16h, g_h16l, N_NODES * D / 4); }
__global__ void k_conv_a() { conv_body(g_agg, g_a16h, g_a16l, N_NODES * D / 4); }

// transpose + split the 18 GNN weight matrices into g_wth/g_wtl
__global__ void k_wprep(const float* __restrict__ epw, const float* __restrict__ emw,
                        const float* __restrict__ npw, const float* __restrict__ nmw) {
    int m = blockIdx.x;
    const float* src;
    if (m < 6) src = epw + (size_t)m * D * D;
    else if (m < 10) src = emw + (size_t)(m - 6) * D * D;
    else if (m < 14) src = npw + (size_t)(m - 10) * D * D;
    else src = nmw + (size_t)(m - 14) * D * D;
    __nv_bfloat16* dh = g_wth + (size_t)m * D * D;
    __nv_bfloat16* dl = g_wtl + (size_t)m * D * D;
    for (int idx = threadIdx.x; idx < D * D; idx += blockDim.x) {
        int k = idx >> 7, c = idx & 127;
        float v = __ldg(src + idx);
        __nv_bfloat16 h = __float2bfloat16(v);
        dh[c * D + k] = h;
        dl[c * D + k] = __float2bfloat16(v - __bfloat162float(h));
    }
}

// =====================================================================
// scalar FFMA2 path (embeddings / output head)
// =====================================================================
#define TM 64
#define XS_STRIDE 132
#define SMEM_BYTES ((TM * XS_STRIDE + D * D) * 4)

__device__ __forceinline__ u64 pack_dup(float x) {
    u64 r;
    asm("mov.b64 %0, {%1, %1};" : "=l"(r) : "f"(x));
    return r;
}
__device__ __forceinline__ void fma2(u64& d, u64 a, u64 b) {
    asm("fma.rn.f32x2 %0, %1, %2, %0;" : "+l"(d) : "l"(a), "l"(b));
}
__device__ __forceinline__ void unpack2(u64 v, float& lo, float& hi) {
    asm("mov.b64 {%0, %1}, %2;" : "=f"(lo), "=f"(hi) : "l"(v));
}
__device__ __forceinline__ void zero_acc2(u64 a2[8][4]) {
#pragma unroll
    for (int i = 0; i < 8; i++)
#pragma unroll
        for (int p = 0; p < 4; p++) a2[i][p] = 0ULL;
}
__device__ __forceinline__ void unpack_acc(const u64 a2[8][4], float acc[8][8]) {
#pragma unroll
    for (int i = 0; i < 8; i++)
#pragma unroll
        for (int p = 0; p < 4; p++) unpack2(a2[i][p], acc[i][2 * p], acc[i][2 * p + 1]);
}
__device__ __forceinline__ void stage_W(float* Ws, const float* __restrict__ src, int n4, int tid) {
    for (int idx = tid; idx < n4; idx += 128)
        ((float4*)Ws)[idx] = __ldg(((const float4*)src) + idx);
}
__device__ __forceinline__ void stage_X_rows(float* Xs, const float* __restrict__ src,
                                             int row0, int M, int tid) {
    for (int idx = tid; idx < TM * 64; idx += 128) {
        int r = idx >> 6, c = idx & 63;
        int row = row0 + r;
        float2 v = make_float2(0.f, 0.f);
        if (row < M) v = __ldg(((const float2*)(src + (size_t)row * D)) + c);
        *(float2*)(Xs + r * XS_STRIDE + 2 * c) = v;
    }
}
__device__ __forceinline__ void gemm128_p2(const float* Xs, const float* Ws,
                                           u64 acc2[8][4], int K, int ty, int tx) {
    const float* xb = Xs + ty * 8 * XS_STRIDE;
    const float* wb = Ws + tx * 8;
#pragma unroll 2
    for (int k0 = 0; k0 < K; k0 += 4) {
        float4 av[8];
#pragma unroll
        for (int i = 0; i < 8; i++)
            av[i] = *(const float4*)(xb + i * XS_STRIDE + k0);
#pragma unroll
        for (int kk = 0; kk < 4; kk++) {
            const ulonglong2* w2 = (const ulonglong2*)(wb + (k0 + kk) * D);
            ulonglong2 b01 = w2[0];
            ulonglong2 b23 = w2[1];
#pragma unroll
            for (int i = 0; i < 8; i++) {
                float a = (kk == 0) ? av[i].x : (kk == 1) ? av[i].y
                        : (kk == 2) ? av[i].z : av[i].w;
                u64 ap = pack_dup(a);
                fma2(acc2[i][0], ap, b01.x);
                fma2(acc2[i][1], ap, b01.y);
                fma2(acc2[i][2], ap, b23.x);
                fma2(acc2[i][3], ap, b23.y);
            }
        }
    }
}
__device__ __forceinline__ void acc_to_X(float* Xs, const float acc[8][8], int ty, int tx) {
#pragma unroll
    for (int i = 0; i < 8; i++)
#pragma unroll
        for (int jp = 0; jp < 4; jp++)
            *(float2*)(Xs + (ty * 8 + i) * XS_STRIDE + tx * 8 + 2 * jp) =
                make_float2(acc[i][2 * jp], acc[i][2 * jp + 1]);
}
__device__ __forceinline__ void mlp_epilogue(float acc[8][8],
                                             const float* __restrict__ bias,
                                             const float* __restrict__ lg,
                                             const float* __restrict__ lb, int tx) {
    float bv[8], gv[8], bev[8];
#pragma unroll
    for (int j = 0; j < 8; j++) {
        bv[j] = __ldg(bias + tx * 8 + j);
        gv[j] = __ldg(lg + tx * 8 + j);
        bev[j] = __ldg(lb + tx * 8 + j);
    }
#pragma unroll
    for (int i = 0; i < 8; i++) {
        float s1 = 0.f, s2 = 0.f;
#pragma unroll
        for (int j = 0; j < 8; j++) {
            float z = gelu_f(acc[i][j] + bv[j]);
            acc[i][j] = z;
            s1 += z;
            s2 += z * z;
        }
#pragma unroll
        for (int o = 8; o >= 1; o >>= 1) {
            s1 += __shfl_xor_sync(0xffffffffu, s1, o);
            s2 += __shfl_xor_sync(0xffffffffu, s2, o);
        }
        float m = s1 * (1.f / D);
        float var = s2 * (1.f / D) - m * m;
        float rs = rsqrtf(var + EPSV);
#pragma unroll
        for (int j = 0; j < 8; j++)
            acc[i][j] = (acc[i][j] - m) * rs * gv[j] + bev[j];
    }
}
__device__ __forceinline__ void plain_store(float* dst, const float acc[8][8],
                                            int row0, int M, int ty, int tx) {
#pragma unroll
    for (int i = 0; i < 8; i++) {
        int row = row0 + ty * 8 + i;
        if (row < M) {
            float2* p = (float2*)(dst + (size_t)row * D + tx * 8);
#pragma unroll
            for (int jp = 0; jp < 4; jp++)
                p[jp] = make_float2(acc[i][2 * jp], acc[i][2 * jp + 1]);
        }
    }
}

// ---------------- CSR construction --------------------------------------------
__global__ void k_zero_deg() {
    int i = blockIdx.x * blockDim.x + threadIdx.x;
    if (i < N_NODES) g_deg[i] = 0;
}
__global__ void k_hist(const int* __restrict__ recv) {
    int i = blockIdx.x * blockDim.x + threadIdx.x;
    if (i < N_EDGES) atomicAdd(&g_deg[recv[i]], 1);
}
__global__ void k_scan() {
    __shared__ int partial[1024];
    const int CH = (N_NODES + 1023) / 1024;
    int t = threadIdx.x;
    int start = t * CH;
    int end = min(start + CH, N_NODES);
    int s = 0;
    for (int i = start; i < end; i++) s += g_deg[i];
    partial[t] = s;
    __syncthreads();
    for (int o = 1; o < 1024; o <<= 1) {
        int v = (t >= o) ? partial[t - o] : 0;
        __syncthreads();
        partial[t] += v;
        __syncthreads();
    }
    int run = partial[t] - s;
    for (int i = start; i < end; i++) {
        int d = g_deg[i];
        g_ptr[i] = run;
        g_off[i] = run;
        g_inv_cnt[i] = 1.0f / (float)max(d, 1);
        run += d;
    }
    if (t == 0) g_ptr[N_NODES] = N_EDGES;
}
__global__ void k_scatter(const int* __restrict__ recv) {
    int i = blockIdx.x * blockDim.x + threadIdx.x;
    if (i < N_EDGES) {
        int p = atomicAdd(&g_off[recv[i]], 1);
        g_idx[p] = i;
    }
}
__global__ void k_sortlists() {
    int n = blockIdx.x * blockDim.x + threadIdx.x;
    if (n >= N_NODES) return;
    int b = g_ptr[n], e2 = g_ptr[n + 1];
    for (int i = b + 1; i < e2; i++) {
        int v = g_idx[i];
        int j = i - 1;
        while (j >= b && g_idx[j] > v) {
            g_idx[j + 1] = g_idx[j];
            j--;
        }
        g_idx[j + 1] = v;
    }
}

// ---------------- embeddings ---------------------------------------------------
__global__ void __launch_bounds__(128, 2) k_node_emb(const float* __restrict__ nodes,
                                                     const float* __restrict__ w,
                                                     const float* __restrict__ b) {
    extern __shared__ float sm[];
    float* Xs = sm;
    float* Ws = sm + TM * XS_STRIDE;
    int tid = threadIdx.x, ty = tid >> 4, tx = tid & 15;
    int row0 = blockIdx.x * TM;
    u64 acc2[8][4];
    zero_acc2(acc2);
    for (int s = 0; s < 3; s++) {
        __syncthreads();
        for (int idx = tid; idx < TM * 48; idx += 128) {
            int r = idx / 48, c = idx % 48;
            int row = row0 + r;
            float2 v = make_float2(0.f, 0.f);
            if (row < N_NODES)
                v = __ldg(((const float2*)(nodes + (size_t)row * KEMB + s * 96)) + c);
            *(float2*)(Xs + r * XS_STRIDE + 2 * c) = v;
        }
        stage_W(Ws, w + s * 96 * D, 96 * 32, tid);
        __syncthreads();
        gemm128_p2(Xs, Ws, acc2, 96, ty, tx);
    }
    float acc[8][8];
    unpack_acc(acc2, acc);
    float bv[8];
#pragma unroll
    for (int j = 0; j < 8; j++) bv[j] = __ldg(b + tx * 8 + j);
#pragma unroll
    for (int i = 0; i < 8; i++)
#pragma unroll
        for (int j = 0; j < 8; j++) acc[i][j] += bv[j];
    plain_store(g_h, acc, row0, N_NODES, ty, tx);
}

__global__ void k_edge_emb(const float* __restrict__ edges,
                           const float* __restrict__ w, const float* __restrict__ b) {
    int idx = blockIdx.x * blockDim.x + threadIdx.x;
    if (idx >= N_EDGES * 32) return;
    int ei = idx >> 5, c4 = idx & 31;
    float e0 = __ldg(edges + ei * 2);
    float e1 = __ldg(edges + ei * 2 + 1);
    float4 w0 = __ldg(((const float4*)w) + c4);
    float4 w1 = __ldg(((const float4*)(w + D)) + c4);
    float4 bb = __ldg(((const float4*)b) + c4);
    float4 r;
    r.x = e0 * w0.x + e1 * w1.x + bb.x;
    r.y = e0 * w0.y + e1 * w1.y + bb.y;
    r.z = e0 * w0.z + e1 * w1.z + bb.z;
    r.w = e0 * w0.w + e1 * w1.w + bb.w;
    ((float4*)(g_e + (size_t)ei * D))[c4] = r;
}

// ---------------- scatter-mean aggregation (pull via CSR) ----------------------
__global__ void __launch_bounds__(256) k_agg() {
    int warp = (blockIdx.x * 256 + threadIdx.x) >> 5;
    int lane = threadIdx.x & 31;
    if (warp >= N_NODES) return;
    int b = g_ptr[warp], e2 = g_ptr[warp + 1];
    float4 a = make_float4(0.f, 0.f, 0.f, 0.f);
    for (int p = b; p < e2; p++) {
        int ei = g_idx[p];
        float4 v = *(const float4*)(g_e + (size_t)ei * D + lane * 4);
        a.x += v.x; a.y += v.y; a.z += v.z; a.w += v.w;
    }
    float ic = g_inv_cnt[warp];
    *(float4*)(g_agg + (size_t)warp * D + lane * 4) =
        make_float4(a.x * ic, a.y * ic, a.z * ic, a.w * ic);
}

// ---------------- output head --------------------------------------------------
__global__ void __launch_bounds__(128, 2) k_out(
    const float* __restrict__ w1, const float* __restrict__ b1,
    const float* __restrict__ lg, const float* __restrict__ lb,
    const float* __restrict__ pw, const float* __restrict__ pb,
    float* __restrict__ out) {
    extern __shared__ float sm[];
    float* Xs = sm;
    float* Ws = sm + TM * XS_STRIDE;
    int tid = threadIdx.x, ty = tid >> 4, tx = tid & 15;
    int row0 = blockIdx.x * TM;
    u64 acc2[8][4];
    zero_acc2(acc2);
    stage_X_rows(Xs, g_h, row0, N_NODES, tid);
    stage_W(Ws, w1, 128 * 32, tid);
    __syncthreads();
    gemm128_p2(Xs, Ws, acc2, 128, ty, tx);
    float acc[8][8];
    unpack_acc(acc2, acc);
    mlp_epilogue(acc, b1, lg, lb, tx);
    __syncthreads();
    acc_to_X(Xs, acc, ty, tx);
    stage_W(Ws, pw, (D * PRED) / 4, tid);
    __syncthreads();
    for (int idx = tid; idx < TM * PRED; idx += 128) {
        int r = idx / PRED, p = idx % PRED;
        int row = row0 + r;
        if (row < N_NODES) {
            float s = __ldg(pb + p);
            const float* xr = Xs + r * XS_STRIDE;
#pragma unroll 4
            for (int k = 0; k < D; k++) s += xr[k] * Ws[k * PRED + p];
            out[(size_t)row * PRED + p] = s;
        }
    }
}

// ---------------- launch -------------------------------------------------------
extern "C" void kernel_launch(void* const* d_in, const int* in_sizes, int n_in,
                              void* d_out, int out_size) {
    const float* nodes = (const float*)d_in[0];
    const float* edges = (const float*)d_in[1];
    const int* senders = (const int*)d_in[2];
    const int* receivers = (const int*)d_in[3];
    const float* w_ne = (const float*)d_in[4];
    const float* b_ne = (const float*)d_in[5];
    const float* w_ee = (const float*)d_in[6];
    const float* b_ee = (const float*)d_in[7];
    const float* epw = (const float*)d_in[8];
    const float* epb = (const float*)d_in[9];
    const float* npw = (const float*)d_in[10];
    const float* npb = (const float*)d_in[11];
    const float* emw = (const float*)d_in[12];
    const float* emb_ = (const float*)d_in[13];
    const float* elg = (const float*)d_in[14];
    const float* elb = (const float*)d_in[15];
    const float* nmw = (const float*)d_in[16];
    const float* nmb = (const float*)d_in[17];
    const float* nlg = (const float*)d_in[18];
    const float* nlb = (const float*)d_in[19];
    const float* ow = (const float*)d_in[20];
    const float* ob = (const float*)d_in[21];
    const float* og = (const float*)d_in[22];
    const float* obeta = (const float*)d_in[23];
    const float* pw = (const float*)d_in[24];
    const float* pb = (const float*)d_in[25];
    float* out = (float*)d_out;

    cudaFuncSetAttribute(k_edge_t, cudaFuncAttributeMaxDynamicSharedMemorySize, TS_BYTES);
    cudaFuncSetAttribute(k_node_t, cudaFuncAttributeMaxDynamicSharedMemorySize, TS_BYTES);
    cudaFuncSetAttribute(k_node_emb, cudaFuncAttributeMaxDynamicSharedMemorySize, SMEM_BYTES);
    cudaFuncSetAttribute(k_out, cudaFuncAttributeMaxDynamicSharedMemorySize, SMEM_BYTES);

    const int n4_e = N_EDGES * D / 4;
    const int n4_n = N_NODES * D / 4;

    // Launch order puts k_edge_t at position 6 so ncu (-s 5 -c 1) captures it.
    k_wprep<<<18, 256>>>(epw, emw, npw, nmw);                               // 1
    k_node_emb<<<(N_NODES + TM - 1) / TM, 128, SMEM_BYTES>>>(nodes, w_ne, b_ne); // 2
    k_edge_emb<<<(N_EDGES * 32 + 255) / 256, 256>>>(edges, w_ee, b_ee);     // 3
    k_conv_e<<<(n4_e + 255) / 256, 256>>>();                                // 4
    k_conv_h<<<(n4_n + 255) / 256, 256>>>();                                // 5
    k_edge_t<<<N_EDGES / TMROWS, NTHR, TS_BYTES>>>(                         // 6 <- profiled
        senders, receivers, 0, 6,
        epb, emb_, elg, elb);

    // CSR build (only needed by k_agg)
    k_zero_deg<<<(N_NODES + 255) / 256, 256>>>();
    k_hist<<<(N_EDGES + 255) / 256, 256>>>(receivers);
    k_scan<<<1, 1024>>>();
    k_scatter<<<(N_EDGES + 255) / 256, 256>>>(receivers);
    k_sortlists<<<(N_NODES + 255) / 256, 256>>>();

    // finish layer 0
    k_agg<<<(N_NODES * 32 + 255) / 256, 256>>>();
    k_conv_a<<<(n4_n + 255) / 256, 256>>>();
    k_node_t<<<(N_NODES + TMROWS - 1) / TMROWS, NTHR, TS_BYTES>>>(
        10, 14, npb, nmb, nlg, nlb);

    // layer 1
    k_conv_e<<<(n4_e + 255) / 256, 256>>>();
    k_conv_h<<<(n4_n + 255) / 256, 256>>>();
    k_edge_t<<<N_EDGES / TMROWS, NTHR, TS_BYTES>>>(
        senders, receivers, 3, 8,
        epb + D, emb_ + 2 * D, elg + 2 * D, elb + 2 * D);
    k_agg<<<(N_NODES * 32 + 255) / 256, 256>>>();
    k_conv_a<<<(n4_n + 255) / 256, 256>>>();
    k_node_t<<<(N_NODES + TMROWS - 1) / TMROWS, NTHR, TS_BYTES>>>(
        12, 16, npb + D, nmb + 2 * D, nlg + 2 * D, nlb + 2 * D);

    // output head
    k_out<<<(N_NODES + TM - 1) / TM, 128, SMEM_BYTES>>>(ow, ob, og, obeta, pw, pb, out);
}